// round 14
// baseline (speedup 1.0000x reference)
#include <cuda_runtime.h>
#include <cuda_fp16.h>
#include <math.h>
#include <stdint.h>

#define SEQ   2048
#define NH    16
#define NKV   4
#define DQK   192
#define DNOPE 128
#define DROPE 64
#define DV    128
#define DM    2048
#define QRANK 1536
#define KVRANK 512
#define NCOMB 2176        // QRANK + 640 (kv_a width padded 576->640)
#define NVALID 2112       // QRANK + 576

// ---------------- scratch (static device globals; allocation-free) ----------------
__device__ float g_qackv[SEQ * NCOMB];     // cols 0..1535 = q_a, 1536..2111 = ckv
__device__ float g_q    [SEQ * NH * DQK];
__device__ float g_kv   [SEQ * NKV * (DNOPE + DV)];

__device__ half g_hid_h [SEQ * DM],       g_hid_l [SEQ * DM];
__device__ half g_qan_h [SEQ * QRANK],    g_qan_l [SEQ * QRANK];
__device__ half g_ckvn_h[SEQ * KVRANK],   g_ckvn_l[SEQ * KVRANK];
__device__ half g_qf_h  [NH * SEQ * DQK], g_qf_l  [NH * SEQ * DQK];
__device__ half g_k     [NKV * SEQ * DQK];
__device__ half g_vT    [NKV * DV * SEQ];
__device__ half g_ao_h  [SEQ * NH * DV],  g_ao_l  [SEQ * NH * DV];
__device__ half g_wcombT[NCOMB * DM];              // rows 0..1535 wq_a^T, 1536.. wkv_a^T
__device__ half g_wqbT [NH * DQK * QRANK];
__device__ half g_wkvbT[NKV*(DNOPE+DV)*KVRANK];
__device__ half g_woT  [DM * NH * DV];

// ---------------- helpers ----------------
__device__ __forceinline__ uint32_t s2u(const void* p) {
    uint32_t a;
    asm("{ .reg .u64 t; cvta.to.shared.u64 t, %1; cvt.u32.u64 %0, t; }"
        : "=r"(a) : "l"(p));
    return a;
}
__device__ __forceinline__ uint32_t pk(half a, half b) {
    unsigned short ua = *(unsigned short*)&a, ub = *(unsigned short*)&b;
    return (uint32_t)ua | ((uint32_t)ub << 16);
}
__device__ __forceinline__ void hsplit(float x, half& h, half& l) {
    h = __float2half_rn(x);
    l = __float2half_rn(x - __half2float(h));
}
__device__ __forceinline__ void ldm4(uint32_t* r, uint32_t addr) {
    asm volatile("ldmatrix.sync.aligned.m8n8.x4.shared.b16 {%0,%1,%2,%3}, [%4];"
        : "=r"(r[0]), "=r"(r[1]), "=r"(r[2]), "=r"(r[3]) : "r"(addr));
}
__device__ __forceinline__ void mma_f16(float* c, const uint32_t* a,
                                        uint32_t b0, uint32_t b1) {
    asm volatile("mma.sync.aligned.m16n8k16.row.col.f32.f16.f16.f32 "
        "{%0,%1,%2,%3}, {%4,%5,%6,%7}, {%8,%9}, {%0,%1,%2,%3};\n"
        : "+f"(c[0]), "+f"(c[1]), "+f"(c[2]), "+f"(c[3])
        : "r"(a[0]), "r"(a[1]), "r"(a[2]), "r"(a[3]), "r"(b0), "r"(b1));
}
__device__ __forceinline__ void cpa16(uint32_t d, const void* g) {
    asm volatile("cp.async.cg.shared.global [%0], [%1], 16;" :: "r"(d), "l"(g));
}
__device__ __forceinline__ void cpa_commit() {
    asm volatile("cp.async.commit_group;" ::: "memory");
}
template<int n>
__device__ __forceinline__ void cpa_wait() {
    asm volatile("cp.async.wait_group %0;" :: "n"(n) : "memory");
}

// ====== fp16 hi/lo 2-pass NT GEMM core, 128x128x32, cp.async double buffer =====
#define SPAD   40
#define TILEB  10240
#define STAGEB 30720
#define OFF_AL 10240
#define OFF_B  20480
#define DSMEM  (2 * STAGEB)

struct GP {
    const half* Ah; const half* Al; const half* B;
    float* C;
    int N, K, lda, ldb, ldc;
    int row0, col0;
};

template<bool NG>
__device__ __forceinline__ void gemm_core(const GP p, char* smem) {
    const int iters = p.K >> 5;
    const int tid = threadIdx.x, lane = tid & 31, wid = tid >> 5;
    const uint32_t sb = s2u(smem);
    const int wm = (wid & 3) * 32;
    const int wn = (wid >> 2) * 64;

    auto issue = [&](int k0, int buf) {
#pragma unroll
        for (int j = 0; j < 6; j++) {
            int i  = j * 256 + tid;
            int t  = i >> 9;
            int r  = (i >> 2) & 127;
            int qu = i & 3;
            const half* gp;
            if (t == 0)      gp = p.Ah + (size_t)(p.row0 + r) * p.lda + k0 + qu * 8;
            else if (t == 1) gp = p.Al + (size_t)(p.row0 + r) * p.lda + k0 + qu * 8;
            else             gp = p.B  + (size_t)(p.col0 + r) * p.ldb + k0 + qu * 8;
            uint32_t d = sb + (uint32_t)buf * STAGEB + (uint32_t)t * TILEB
                         + ((uint32_t)r * SPAD + qu * 8) * 2;
            cpa16(d, gp);
        }
    };

    float acc[2][8][4];
#pragma unroll
    for (int mt = 0; mt < 2; mt++)
#pragma unroll
        for (int nt = 0; nt < 8; nt++)
#pragma unroll
            for (int i = 0; i < 4; i++) acc[mt][nt][i] = 0.f;

    auto compute = [&](int buf) {
        const uint32_t ba = sb + (uint32_t)buf * STAGEB;
#pragma unroll
        for (int s16 = 0; s16 < 32; s16 += 16) {
            uint32_t ah[2][4], al[2][4];
#pragma unroll
            for (int mt = 0; mt < 2; mt++) {
                uint32_t addr = ba + (((uint32_t)(wm + mt * 16 + (lane & 15))) * SPAD
                                      + s16 + ((lane >> 4) << 3)) * 2;
                ldm4(ah[mt], addr);
                ldm4(al[mt], addr + OFF_AL);
            }
#pragma unroll
            for (int pp = 0; pp < 4; pp++) {
                const int g = lane >> 3;
                uint32_t addr = ba + OFF_B +
                    (((uint32_t)(wn + pp * 16 + (lane & 7) + ((g >> 1) << 3))) * SPAD
                     + s16 + ((g & 1) << 3)) * 2;
                uint32_t bh[4];
                ldm4(bh, addr);
#pragma unroll
                for (int mt = 0; mt < 2; mt++) {
                    mma_f16(acc[mt][2*pp],   ah[mt], bh[0], bh[1]);
                    mma_f16(acc[mt][2*pp],   al[mt], bh[0], bh[1]);
                    mma_f16(acc[mt][2*pp+1], ah[mt], bh[2], bh[3]);
                    mma_f16(acc[mt][2*pp+1], al[mt], bh[2], bh[3]);
                }
            }
        }
    };

    issue(0, 0);
    cpa_commit();
    if (iters > 1) issue(32, 1);
    cpa_commit();

    for (int it = 0; it < iters; ++it) {
        cpa_wait<1>();
        __syncthreads();
        compute(it & 1);
        __syncthreads();
        if (it + 2 < iters) issue((it + 2) << 5, it & 1);
        cpa_commit();
    }

    const int grp = lane >> 2, tig = lane & 3;
#pragma unroll
    for (int mt = 0; mt < 2; mt++) {
#pragma unroll
        for (int nt = 0; nt < 8; nt++) {
            int r = p.row0 + wm + mt * 16 + grp;
            int c = p.col0 + wn + nt * 8 + 2 * tig;
            if (NG && c >= p.N) continue;
            *(float2*)&p.C[(size_t)r * p.ldc + c] =
                make_float2(acc[mt][nt][0], acc[mt][nt][1]);
            *(float2*)&p.C[(size_t)(r + 8) * p.ldc + c] =
                make_float2(acc[mt][nt][2], acc[mt][nt][3]);
        }
    }
}

template<bool NG>
__global__ __launch_bounds__(256, 2)
void ntgemm(const half* __restrict__ Ah, const half* __restrict__ Al,
            const half* __restrict__ B, float* __restrict__ C,
            int N, int K, int lda, int ldb, int ldc) {
    extern __shared__ __align__(16) char smem[];
    GP p{Ah, Al, B, C, N, K, lda, ldb, ldc,
         (int)blockIdx.y * 128, (int)blockIdx.x * 128};
    gemm_core<NG>(p, smem);
}

// dual GEMM: col tiles [0,24) -> set0 (wq_b), [24,32) -> set1 (wkv_b)
__global__ __launch_bounds__(256, 2)
void ntgemm_dual(const half* __restrict__ A0h, const half* __restrict__ A0l,
                 const half* __restrict__ B0, float* __restrict__ C0,
                 const half* __restrict__ A1h, const half* __restrict__ A1l,
                 const half* __restrict__ B1, float* __restrict__ C1) {
    extern __shared__ __align__(16) char smem[];
    const int bx = blockIdx.x;
    GP p;
    if (bx < 24) {
        p = GP{A0h, A0l, B0, C0, NH*DQK, QRANK, QRANK, QRANK, NH*DQK,
               (int)blockIdx.y * 128, bx * 128};
    } else {
        p = GP{A1h, A1l, B1, C1, NKV*(DNOPE+DV), KVRANK, KVRANK, KVRANK,
               NKV*(DNOPE+DV), (int)blockIdx.y * 128, (bx - 24) * 128};
    }
    gemm_core<false>(p, smem);
}

// ================= fused flash attention ======================================
#define QPAD 200
#define KPAD 200
#define VPAD 72
#define SQH_OFF 0
#define SQL_OFF 51200
#define SK_OFF  102400
#define SK_SZ   25600
#define SV_OFF  153600
#define SV_SZ   18432
#define FA_SMEM 190464

__global__ __launch_bounds__(256, 1)
void flash_attn(const half* __restrict__ Qh, const half* __restrict__ Ql,
                const half* __restrict__ K, const half* __restrict__ VT,
                half* __restrict__ AOh, half* __restrict__ AOl, float scale) {
    extern __shared__ __align__(16) char smem[];
    const int qt = (int)gridDim.x - 1 - (int)blockIdx.x;   // heavy tiles first
    const int h = blockIdx.y;
    const int q0 = qt * 128;
    const int nc = 2 * qt + 2;
    const int kh = h >> 2;

    const int tid = threadIdx.x, lane = tid & 31, wid = tid >> 5;
    const int grp = lane >> 2, tig = lane & 3;
    const uint32_t sb = s2u(smem);

    const half* Qhb = Qh + ((size_t)h * SEQ + q0) * DQK;
    const half* Qlb = Ql + ((size_t)h * SEQ + q0) * DQK;
    const half* Kb  = K  + (size_t)kh * SEQ * DQK;
    const half* Vb  = VT + (size_t)kh * DV * SEQ;

#pragma unroll
    for (int j = 0; j < 24; j++) {
        int idx = j * 256 + tid;
        int t   = idx / 3072;
        int rem = idx - t * 3072;
        int r   = rem / 24;
        int cc  = (rem % 24) * 8;
        const half* src = (t ? Qlb : Qhb) + (size_t)r * DQK + cc;
        uint32_t dst = sb + (t ? SQL_OFF : SQH_OFF) + ((uint32_t)r * QPAD + cc) * 2;
        cpa16(dst, src);
    }

    auto issue_kv = [&](int c, int buf) {
        const int k0 = c * 64;
#pragma unroll
        for (int j = 0; j < 10; j++) {
            int idx = j * 256 + tid;
            if (idx < 1536) {
                int r = idx / 24, cc = (idx % 24) * 8;
                cpa16(sb + SK_OFF + (uint32_t)buf * SK_SZ + ((uint32_t)r * KPAD + cc) * 2,
                      Kb + (size_t)(k0 + r) * DQK + cc);
            } else {
                int i2 = idx - 1536;
                int d = i2 / 8, cc = (i2 % 8) * 8;
                cpa16(sb + SV_OFF + (uint32_t)buf * SV_SZ + ((uint32_t)d * VPAD + cc) * 2,
                      Vb + (size_t)d * SEQ + k0 + cc);
            }
        }
    };

    issue_kv(0, 0);
    cpa_commit();
    if (nc > 1) issue_kv(1, 1);
    cpa_commit();

    float O[16][4];
#pragma unroll
    for (int dt = 0; dt < 16; dt++)
#pragma unroll
        for (int i = 0; i < 4; i++) O[dt][i] = 0.f;
    float m0 = -1e30f, m1 = -1e30f, l0 = 0.f, l1 = 0.f;

    const int row0 = q0 + wid * 16 + grp;
    const int row1 = row0 + 8;

    for (int c = 0; c < nc; ++c) {
        cpa_wait<1>();
        __syncthreads();
        const int buf = c & 1;
        const uint32_t kbase = sb + SK_OFF + (uint32_t)buf * SK_SZ;
        const uint32_t vbase = sb + SV_OFF + (uint32_t)buf * SV_SZ;
        const int k0 = c * 64;

        float S[8][4];
#pragma unroll
        for (int nt = 0; nt < 8; nt++)
#pragma unroll
            for (int i = 0; i < 4; i++) S[nt][i] = 0.f;

#pragma unroll
        for (int s16 = 0; s16 < DQK; s16 += 16) {
            uint32_t ah[4], al[4];
            uint32_t aaddr = sb + (((uint32_t)(wid * 16 + (lane & 15))) * QPAD
                                   + s16 + ((lane >> 4) << 3)) * 2;
            ldm4(ah, aaddr + SQH_OFF);
            ldm4(al, aaddr + SQL_OFF);
#pragma unroll
            for (int p = 0; p < 4; p++) {
                const int g = lane >> 3;
                uint32_t baddr = kbase +
                    (((uint32_t)(p * 16 + (lane & 7) + ((g >> 1) << 3))) * KPAD
                     + s16 + ((g & 1) << 3)) * 2;
                uint32_t bh[4];
                ldm4(bh, baddr);
                mma_f16(S[2*p],   ah, bh[0], bh[1]);
                mma_f16(S[2*p],   al, bh[0], bh[1]);
                mma_f16(S[2*p+1], ah, bh[2], bh[3]);
                mma_f16(S[2*p+1], al, bh[2], bh[3]);
            }
        }

#pragma unroll
        for (int nt = 0; nt < 8; nt++)
#pragma unroll
            for (int i = 0; i < 4; i++) S[nt][i] *= scale;
        if (c >= nc - 2) {
#pragma unroll
            for (int nt = 0; nt < 8; nt++) {
                int col = k0 + (nt >> 1) * 16 + (nt & 1) * 8 + tig * 2;
                if (col     > row0) S[nt][0] = -1e30f;
                if (col + 1 > row0) S[nt][1] = -1e30f;
                if (col     > row1) S[nt][2] = -1e30f;
                if (col + 1 > row1) S[nt][3] = -1e30f;
            }
        }

        float cm0 = -1e30f, cm1 = -1e30f;
#pragma unroll
        for (int nt = 0; nt < 8; nt++) {
            cm0 = fmaxf(cm0, fmaxf(S[nt][0], S[nt][1]));
            cm1 = fmaxf(cm1, fmaxf(S[nt][2], S[nt][3]));
        }
        cm0 = fmaxf(cm0, __shfl_xor_sync(0xffffffff, cm0, 1));
        cm0 = fmaxf(cm0, __shfl_xor_sync(0xffffffff, cm0, 2));
        cm1 = fmaxf(cm1, __shfl_xor_sync(0xffffffff, cm1, 1));
        cm1 = fmaxf(cm1, __shfl_xor_sync(0xffffffff, cm1, 2));
        float mn0 = fmaxf(m0, cm0), mn1 = fmaxf(m1, cm1);
        float a0 = __expf(m0 - mn0), a1 = __expf(m1 - mn1);
        m0 = mn0; m1 = mn1;

        float rs0 = 0.f, rs1 = 0.f;
#pragma unroll
        for (int nt = 0; nt < 8; nt++) {
            S[nt][0] = __expf(S[nt][0] - mn0);
            S[nt][1] = __expf(S[nt][1] - mn0);
            S[nt][2] = __expf(S[nt][2] - mn1);
            S[nt][3] = __expf(S[nt][3] - mn1);
            rs0 += S[nt][0] + S[nt][1];
            rs1 += S[nt][2] + S[nt][3];
        }
        rs0 += __shfl_xor_sync(0xffffffff, rs0, 1);
        rs0 += __shfl_xor_sync(0xffffffff, rs0, 2);
        rs1 += __shfl_xor_sync(0xffffffff, rs1, 1);
        rs1 += __shfl_xor_sync(0xffffffff, rs1, 2);
        l0 = l0 * a0 + rs0;
        l1 = l1 * a1 + rs1;

#pragma unroll
        for (int dt = 0; dt < 16; dt++) {
            O[dt][0] *= a0; O[dt][1] *= a0;
            O[dt][2] *= a1; O[dt][3] *= a1;
        }

#pragma unroll
        for (int kk = 0; kk < 4; kk++) {
            uint32_t pah[4], pal[4];
            half p0h, p0l, p1h, p1l;
            hsplit(S[2*kk][0], p0h, p0l);  hsplit(S[2*kk][1], p1h, p1l);
            pah[0] = pk(p0h, p1h); pal[0] = pk(p0l, p1l);
            hsplit(S[2*kk][2], p0h, p0l);  hsplit(S[2*kk][3], p1h, p1l);
            pah[1] = pk(p0h, p1h); pal[1] = pk(p0l, p1l);
            hsplit(S[2*kk+1][0], p0h, p0l); hsplit(S[2*kk+1][1], p1h, p1l);
            pah[2] = pk(p0h, p1h); pal[2] = pk(p0l, p1l);
            hsplit(S[2*kk+1][2], p0h, p0l); hsplit(S[2*kk+1][3], p1h, p1l);
            pah[3] = pk(p0h, p1h); pal[3] = pk(p0l, p1l);
#pragma unroll
            for (int p2 = 0; p2 < 8; p2++) {
                const int g = lane >> 3;
                uint32_t baddr = vbase +
                    (((uint32_t)(p2 * 16 + (lane & 7) + ((g >> 1) << 3))) * VPAD
                     + kk * 16 + ((g & 1) << 3)) * 2;
                uint32_t bv[4];
                ldm4(bv, baddr);
                mma_f16(O[2*p2],   pah, bv[0], bv[1]);
                mma_f16(O[2*p2],   pal, bv[0], bv[1]);
                mma_f16(O[2*p2+1], pah, bv[2], bv[3]);
                mma_f16(O[2*p2+1], pal, bv[2], bv[3]);
            }
        }

        __syncthreads();
        if (c + 2 < nc) issue_kv(c + 2, buf);
        cpa_commit();
    }

    const float i0 = 1.f / l0, i1 = 1.f / l1;
#pragma unroll
    for (int dt = 0; dt < 16; dt++) {
        int d = dt * 8 + tig * 2;
        half h0, lo0, h1, lo1;
        hsplit(O[dt][0] * i0, h0, lo0);
        hsplit(O[dt][1] * i0, h1, lo1);
        size_t o0 = (size_t)row0 * (NH * DV) + h * DV + d;
        *(uint32_t*)&AOh[o0] = pk(h0, h1);
        *(uint32_t*)&AOl[o0] = pk(lo0, lo1);
        hsplit(O[dt][2] * i1, h0, lo0);
        hsplit(O[dt][3] * i1, h1, lo1);
        size_t o1 = (size_t)row1 * (NH * DV) + h * DV + d;
        *(uint32_t*)&AOh[o1] = pk(h0, h1);
        *(uint32_t*)&AOl[o1] = pk(lo0, lo1);
    }
}

// ---------------- elementwise fp32 -> fp16 hi/lo split ----------------
__global__ __launch_bounds__(256)
void split_pair(const float* __restrict__ X, half* __restrict__ H,
                half* __restrict__ L, int n) {
    int i = (blockIdx.x * 256 + threadIdx.x) * 4;
    if (i >= n) return;
    float4 v = *(const float4*)&X[i];
    half h0,l0,h1,l1,h2,l2,h3,l3;
    hsplit(v.x,h0,l0); hsplit(v.y,h1,l1); hsplit(v.z,h2,l2); hsplit(v.w,h3,l3);
    *(uint2*)&H[i] = make_uint2(pk(h0,h1), pk(h2,h3));
    *(uint2*)&L[i] = make_uint2(pk(l0,l1), pk(l2,l3));
}

// -------- weight transpose: W[K,N] -> T[(rowoff+n)*ldt + k] fp16 --------
__global__ __launch_bounds__(256)
void wsplitT(const float* __restrict__ W, half* __restrict__ T,
             int K, int N, int rowoff) {
    __shared__ float t[32][33];
    const int n0 = blockIdx.x * 32, k0 = blockIdx.y * 32;
    const int tx = threadIdx.x & 31, ty = threadIdx.x >> 5;
#pragma unroll
    for (int i = 0; i < 4; i++) {
        int k = k0 + ty + i * 8, n = n0 + tx;
        t[ty + i * 8][tx] = (n < N) ? W[(size_t)k * N + n] : 0.f;
    }
    __syncthreads();
#pragma unroll
    for (int i = 0; i < 4; i++) {
        int n = n0 + ty + i * 8, k = k0 + tx;
        T[(size_t)(rowoff + n) * K + k] = __float2half_rn(t[tx][ty + i * 8]);
    }
}

// ---------------- rms norm -> fp16 hi/lo ----------------
__global__ __launch_bounds__(256)
void rmsnorm_split(const float* __restrict__ X, half* __restrict__ Yh,
                   half* __restrict__ Yl, const float* __restrict__ W,
                   int n, int ldx, int ldy) {
    const int r = blockIdx.x;
    const float* x = X + (size_t)r * ldx;
    const int tid = threadIdx.x;
    __shared__ float red[256];

    float ss = 0.f;
    for (int j = tid; j < n; j += 256) { float v = x[j]; ss += v * v; }
    red[tid] = ss; __syncthreads();
    for (int s = 128; s > 0; s >>= 1) {
        if (tid < s) red[tid] += red[tid + s];
        __syncthreads();
    }
    const float rinv = rsqrtf(red[0] / (float)n + 1e-6f);
    for (int j = tid; j < n; j += 256) {
        half h, l;
        hsplit(x[j] * rinv * W[j], h, l);
        Yh[(size_t)r * ldy + j] = h;
        Yl[(size_t)r * ldy + j] = l;
    }
}

// ---------------- RoPE + head gather -> fp16 (Q split; K,V single) ----------------
__global__ __launch_bounds__(256)
void rope_gather_split(const float* __restrict__ q,
                       const float* __restrict__ kv,
                       const float* __restrict__ ckv, int ldckv,
                       const float* __restrict__ cosT, const float* __restrict__ sinT,
                       const int* __restrict__ pos,
                       half* __restrict__ qfh, half* __restrict__ qfl,
                       half* __restrict__ kk, half* __restrict__ vt) {
    const int s = blockIdx.x;
    const int p = pos[s];
    const float* c  = cosT + (size_t)p * DROPE;
    const float* sn = sinT + (size_t)p * DROPE;

    for (int i = threadIdx.x; i < NH * DQK; i += 256) {
        int h = i / DQK, d = i % DQK;
        const float* qr = q + (size_t)s * NH * DQK + h * DQK;
        float val;
        if (d < DNOPE) val = qr[d];
        else {
            int dr = d - DNOPE;
            float x  = qr[d];
            float rh = (dr < DROPE / 2) ? -qr[DNOPE + dr + DROPE / 2]
                                        :  qr[DNOPE + dr - DROPE / 2];
            val = x * c[dr] + rh * sn[dr];
        }
        half hh, ll;
        hsplit(val, hh, ll);
        size_t o = ((size_t)h * SEQ + s) * DQK + d;
        qfh[o] = hh; qfl[o] = ll;
    }
    for (int i = threadIdx.x; i < NKV * DQK; i += 256) {
        int kh2 = i / DQK, d = i % DQK;
        float val;
        if (d < DNOPE) val = kv[(size_t)s * NKV * (DNOPE + DV) + kh2 * (DNOPE + DV) + d];
        else {
            int dr = d - DNOPE;
            const float* kr = ckv + (size_t)s * ldckv + KVRANK;
            float x  = kr[dr];
            float rh = (dr < DROPE / 2) ? -kr[dr + DROPE / 2] : kr[dr - DROPE / 2];
            val = x * c[dr] + rh * sn[dr];
        }
        kk[((size_t)kh2 * SEQ + s) * DQK + d] = __float2half_rn(val);
    }
    for (int i = threadIdx.x; i < NKV * DV; i += 256) {
        int kh2 = i / DV, d = i % DV;
        float val = kv[(size_t)s * NKV * (DNOPE + DV) + kh2 * (DNOPE + DV) + DNOPE + d];
        vt[((size_t)kh2 * DV + d) * SEQ + s] = __float2half_rn(val);
    }
}

// ---------------- launch ----------------
extern "C" void kernel_launch(void* const* d_in, const int* in_sizes, int n_in,
                              void* d_out, int out_size) {
    const float* hidden    = (const float*)d_in[0];
    const float* cosT      = (const float*)d_in[1];
    const float* sinT      = (const float*)d_in[2];
    const float* wq_a      = (const float*)d_in[3];
    const float* q_a_ln_w  = (const float*)d_in[4];
    const float* wq_b      = (const float*)d_in[5];
    const float* wkv_a     = (const float*)d_in[6];
    const float* kv_a_ln_w = (const float*)d_in[7];
    const float* wkv_b     = (const float*)d_in[8];
    const float* wo        = (const float*)d_in[9];
    const int*   cpos      = (const int*)d_in[10];
    float* out = (float*)d_out;

    float *qackv, *q, *kv;
    half *hidh, *hidl, *qanh, *qanl, *ckvnh, *ckvnl, *qfh, *qfl, *kk, *vt;
    half *aoh, *aol;
    half *wcombT, *wqbT, *wkvbT, *woT;

    cudaGetSymbolAddress((void**)&qackv, g_qackv);
    cudaGetSymbolAddress((void**)&q,     g_q);
    cudaGetSymbolAddress((void**)&kv,    g_kv);
    cudaGetSymbolAddress((void**)&hidh,  g_hid_h);  cudaGetSymbolAddress((void**)&hidl,  g_hid_l);
    cudaGetSymbolAddress((void**)&qanh,  g_qan_h);  cudaGetSymbolAddress((void**)&qanl,  g_qan_l);
    cudaGetSymbolAddress((void**)&ckvnh, g_ckvn_h); cudaGetSymbolAddress((void**)&ckvnl, g_ckvn_l);
    cudaGetSymbolAddress((void**)&qfh,   g_qf_h);   cudaGetSymbolAddress((void**)&qfl,   g_qf_l);
    cudaGetSymbolAddress((void**)&kk,    g_k);
    cudaGetSymbolAddress((void**)&vt,    g_vT);
    cudaGetSymbolAddress((void**)&aoh,   g_ao_h);   cudaGetSymbolAddress((void**)&aol,   g_ao_l);
    cudaGetSymbolAddress((void**)&wcombT,g_wcombT);
    cudaGetSymbolAddress((void**)&wqbT,  g_wqbT);
    cudaGetSymbolAddress((void**)&wkvbT, g_wkvbT);
    cudaGetSymbolAddress((void**)&woT,   g_woT);

    cudaFuncSetAttribute(ntgemm<false>,
        cudaFuncAttributeMaxDynamicSharedMemorySize, DSMEM);
    cudaFuncSetAttribute(ntgemm<true>,
        cudaFuncAttributeMaxDynamicSharedMemorySize, DSMEM);
    cudaFuncSetAttribute(ntgemm_dual,
        cudaFuncAttributeMaxDynamicSharedMemorySize, DSMEM);
    cudaFuncSetAttribute(flash_attn,
        cudaFuncAttributeMaxDynamicSharedMemorySize, FA_SMEM);

    // 0) operand conversion
    split_pair<<<SEQ*DM/1024, 256>>>(hidden, hidh, hidl, SEQ*DM);
    wsplitT<<<dim3(QRANK/32, DM/32), 256>>>(wq_a,  wcombT, DM,    QRANK, 0);
    wsplitT<<<dim3((576+31)/32*32/32, DM/32), 256>>>(wkv_a, wcombT, DM, KVRANK+DROPE, QRANK);
    wsplitT<<<dim3(NH*DQK/32, QRANK/32), 256>>>(wq_b, wqbT, QRANK, NH*DQK, 0);
    wsplitT<<<dim3(NKV*(DNOPE+DV)/32, KVRANK/32), 256>>>(wkv_b, wkvbT, KVRANK, NKV*(DNOPE+DV), 0);
    wsplitT<<<dim3(DM/32, NH*DV/32), 256>>>(wo, woT, NH*DV, DM, 0);

    // 1) [q_a | ckv] = hidden @ [wq_a | wkv_a]   (fused, N=2112 valid of 2176)
    ntgemm<true><<<dim3(NCOMB/128, SEQ/128), 256, DSMEM>>>(
        hidh, hidl, wcombT, qackv, NVALID, DM, DM, DM, NCOMB);
    // 2) rmsnorms -> fp16 splits
    rmsnorm_split<<<SEQ, 256>>>(qackv, qanh, qanl, q_a_ln_w, QRANK, NCOMB, QRANK);
    rmsnorm_split<<<SEQ, 256>>>(qackv + QRANK, ckvnh, ckvnl, kv_a_ln_w,
                                KVRANK, NCOMB, KVRANK);
    // 3) dual GEMM: q = qan @ wq_b  AND  kv = ckvn @ wkv_b
    ntgemm_dual<<<dim3(32, SEQ/128), 256, DSMEM>>>(
        qanh, qanl, wqbT, q, ckvnh, ckvnl, wkvbT, kv);
    // 4) RoPE + gather -> fp16 (Q split; K,V single; V transposed)
    rope_gather_split<<<SEQ, 256>>>(q, kv, qackv + QRANK, NCOMB,
                                    cosT, sinT, cpos, qfh, qfl, kk, vt);
    // 5) fused flash attention -> ao hi/lo (heavy q-tiles first)
    flash_attn<<<dim3(SEQ/128, NH), 256, FA_SMEM>>>(
        qfh, qfl, kk, vt, aoh, aol, rsqrtf((float)DQK));
    // 6) out = ao @ wo
    ntgemm<false><<<dim3(DM/128, SEQ/128), 256, DSMEM>>>(
        aoh, aol, woT, out, DM, NH*DV, NH*DV, NH*DV, DM);
}

// round 15
// speedup vs baseline: 1.6053x; 1.6053x over previous
#include <cuda_runtime.h>
#include <cuda_fp16.h>
#include <math.h>
#include <stdint.h>

#define SEQ   2048
#define NH    16
#define NKV   4
#define DQK   192
#define DNOPE 128
#define DROPE 64
#define DV    128
#define DM    2048
#define QRANK 1536
#define KVRANK 512
#define NCOMB 2176        // QRANK + 640 (kv_a width padded 576->640)
#define NVALID 2112       // QRANK + 576

// ---------------- scratch (static device globals; allocation-free) ----------------
__device__ float g_qackv[SEQ * NCOMB];     // cols 0..1535 = q_a, 1536..2111 = ckv
__device__ float g_q    [SEQ * NH * DQK];
__device__ float g_kv   [SEQ * NKV * (DNOPE + DV)];

__device__ half g_hid_h [SEQ * DM],       g_hid_l [SEQ * DM];
__device__ half g_qan_h [SEQ * QRANK],    g_qan_l [SEQ * QRANK];
__device__ half g_ckvn_h[SEQ * KVRANK],   g_ckvn_l[SEQ * KVRANK];
__device__ half g_qf_h  [NH * SEQ * DQK], g_qf_l  [NH * SEQ * DQK];
__device__ half g_k     [NKV * SEQ * DQK];
__device__ half g_vT    [NKV * DV * SEQ];
__device__ half g_ao_h  [SEQ * NH * DV],  g_ao_l  [SEQ * NH * DV];
__device__ half g_wcombT[NCOMB * DM];              // rows 0..1535 wq_a^T, 1536.. wkv_a^T
__device__ half g_wqbT [NH * DQK * QRANK];
__device__ half g_wkvbT[NKV*(DNOPE+DV)*KVRANK];
__device__ half g_woT  [DM * NH * DV];

// ---------------- helpers ----------------
__device__ __forceinline__ uint32_t s2u(const void* p) {
    uint32_t a;
    asm("{ .reg .u64 t; cvta.to.shared.u64 t, %1; cvt.u32.u64 %0, t; }"
        : "=r"(a) : "l"(p));
    return a;
}
__device__ __forceinline__ uint32_t pk(half a, half b) {
    unsigned short ua = *(unsigned short*)&a, ub = *(unsigned short*)&b;
    return (uint32_t)ua | ((uint32_t)ub << 16);
}
__device__ __forceinline__ void hsplit(float x, half& h, half& l) {
    h = __float2half_rn(x);
    l = __float2half_rn(x - __half2float(h));
}
__device__ __forceinline__ void ldm4(uint32_t* r, uint32_t addr) {
    asm volatile("ldmatrix.sync.aligned.m8n8.x4.shared.b16 {%0,%1,%2,%3}, [%4];"
        : "=r"(r[0]), "=r"(r[1]), "=r"(r[2]), "=r"(r[3]) : "r"(addr));
}
__device__ __forceinline__ void mma_f16(float* c, const uint32_t* a,
                                        uint32_t b0, uint32_t b1) {
    asm volatile("mma.sync.aligned.m16n8k16.row.col.f32.f16.f16.f32 "
        "{%0,%1,%2,%3}, {%4,%5,%6,%7}, {%8,%9}, {%0,%1,%2,%3};\n"
        : "+f"(c[0]), "+f"(c[1]), "+f"(c[2]), "+f"(c[3])
        : "r"(a[0]), "r"(a[1]), "r"(a[2]), "r"(a[3]), "r"(b0), "r"(b1));
}
__device__ __forceinline__ void cpa16(uint32_t d, const void* g) {
    asm volatile("cp.async.cg.shared.global [%0], [%1], 16;" :: "r"(d), "l"(g));
}
__device__ __forceinline__ void cpa_commit() {
    asm volatile("cp.async.commit_group;" ::: "memory");
}
template<int n>
__device__ __forceinline__ void cpa_wait() {
    asm volatile("cp.async.wait_group %0;" :: "n"(n) : "memory");
}

// ====== fp16 hi/lo 2-pass NT GEMM, 128x128x32, cp.async double buffer =========
// (R13-verified body — direct parameters, no struct)
#define SPAD   40
#define TILEB  10240
#define STAGEB 30720
#define OFF_AL 10240
#define OFF_B  20480
#define DSMEM  (2 * STAGEB)

template<bool NG>
__global__ __launch_bounds__(256, 2)
void ntgemm(const half* __restrict__ Ah, const half* __restrict__ Al,
            const half* __restrict__ B, float* __restrict__ C,
            int N, int K, int lda, int ldb, int ldc) {
    extern __shared__ __align__(16) char smem[];

    const int row0 = blockIdx.y * 128;
    const int col0 = blockIdx.x * 128;
    const int iters = K >> 5;

    const int tid = threadIdx.x, lane = tid & 31, wid = tid >> 5;
    const uint32_t sb = s2u(smem);

    const int wm = (wid & 3) * 32;
    const int wn = (wid >> 2) * 64;

    auto issue = [&](int k0, int buf) {
#pragma unroll
        for (int j = 0; j < 6; j++) {
            int i  = j * 256 + tid;
            int t  = i >> 9;
            int r  = (i >> 2) & 127;
            int qu = i & 3;
            const half* gp;
            if (t == 0)      gp = Ah + (size_t)(row0 + r) * lda + k0 + qu * 8;
            else if (t == 1) gp = Al + (size_t)(row0 + r) * lda + k0 + qu * 8;
            else             gp = B  + (size_t)(col0 + r) * ldb + k0 + qu * 8;
            uint32_t d = sb + (uint32_t)buf * STAGEB + (uint32_t)t * TILEB
                         + ((uint32_t)r * SPAD + qu * 8) * 2;
            cpa16(d, gp);
        }
    };

    float acc[2][8][4];
#pragma unroll
    for (int mt = 0; mt < 2; mt++)
#pragma unroll
        for (int nt = 0; nt < 8; nt++)
#pragma unroll
            for (int i = 0; i < 4; i++) acc[mt][nt][i] = 0.f;

    auto compute = [&](int buf) {
        const uint32_t ba = sb + (uint32_t)buf * STAGEB;
#pragma unroll
        for (int s16 = 0; s16 < 32; s16 += 16) {
            uint32_t ah[2][4], al[2][4];
#pragma unroll
            for (int mt = 0; mt < 2; mt++) {
                uint32_t addr = ba + (((uint32_t)(wm + mt * 16 + (lane & 15))) * SPAD
                                      + s16 + ((lane >> 4) << 3)) * 2;
                ldm4(ah[mt], addr);
                ldm4(al[mt], addr + OFF_AL);
            }
#pragma unroll
            for (int p = 0; p < 4; p++) {
                const int g = lane >> 3;
                uint32_t addr = ba + OFF_B +
                    (((uint32_t)(wn + p * 16 + (lane & 7) + ((g >> 1) << 3))) * SPAD
                     + s16 + ((g & 1) << 3)) * 2;
                uint32_t bh[4];
                ldm4(bh, addr);
#pragma unroll
                for (int mt = 0; mt < 2; mt++) {
                    mma_f16(acc[mt][2*p],   ah[mt], bh[0], bh[1]);
                    mma_f16(acc[mt][2*p],   al[mt], bh[0], bh[1]);
                    mma_f16(acc[mt][2*p+1], ah[mt], bh[2], bh[3]);
                    mma_f16(acc[mt][2*p+1], al[mt], bh[2], bh[3]);
                }
            }
        }
    };

    issue(0, 0);
    cpa_commit();
    if (iters > 1) issue(32, 1);
    cpa_commit();

    for (int it = 0; it < iters; ++it) {
        cpa_wait<1>();
        __syncthreads();
        compute(it & 1);
        __syncthreads();
        if (it + 2 < iters) issue((it + 2) << 5, it & 1);
        cpa_commit();
    }

    const int grp = lane >> 2, tig = lane & 3;
#pragma unroll
    for (int mt = 0; mt < 2; mt++) {
#pragma unroll
        for (int nt = 0; nt < 8; nt++) {
            int r = row0 + wm + mt * 16 + grp;
            int c = col0 + wn + nt * 8 + 2 * tig;
            if (NG && c >= N) continue;
            *(float2*)&C[(size_t)r * ldc + c] =
                make_float2(acc[mt][nt][0], acc[mt][nt][1]);
            *(float2*)&C[(size_t)(r + 8) * ldc + c] =
                make_float2(acc[mt][nt][2], acc[mt][nt][3]);
        }
    }
}

// ================= fused flash attention (R13 body, heavy tiles first) ========
#define QPAD 200
#define KPAD 200
#define VPAD 72
#define SQH_OFF 0
#define SQL_OFF 51200
#define SK_OFF  102400
#define SK_SZ   25600
#define SV_OFF  153600
#define SV_SZ   18432
#define FA_SMEM 190464

__global__ __launch_bounds__(256, 1)
void flash_attn(const half* __restrict__ Qh, const half* __restrict__ Ql,
                const half* __restrict__ K, const half* __restrict__ VT,
                half* __restrict__ AOh, half* __restrict__ AOl, float scale) {
    extern __shared__ __align__(16) char smem[];
    const int qt = (int)gridDim.x - 1 - (int)blockIdx.x;   // heavy tiles first
    const int h = blockIdx.y;
    const int q0 = qt * 128;
    const int nc = 2 * qt + 2;
    const int kh = h >> 2;

    const int tid = threadIdx.x, lane = tid & 31, wid = tid >> 5;
    const int grp = lane >> 2, tig = lane & 3;
    const uint32_t sb = s2u(smem);

    const half* Qhb = Qh + ((size_t)h * SEQ + q0) * DQK;
    const half* Qlb = Ql + ((size_t)h * SEQ + q0) * DQK;
    const half* Kb  = K  + (size_t)kh * SEQ * DQK;
    const half* Vb  = VT + (size_t)kh * DV * SEQ;

#pragma unroll
    for (int j = 0; j < 24; j++) {
        int idx = j * 256 + tid;
        int t   = idx / 3072;
        int rem = idx - t * 3072;
        int r   = rem / 24;
        int cc  = (rem % 24) * 8;
        const half* src = (t ? Qlb : Qhb) + (size_t)r * DQK + cc;
        uint32_t dst = sb + (t ? SQL_OFF : SQH_OFF) + ((uint32_t)r * QPAD + cc) * 2;
        cpa16(dst, src);
    }

    auto issue_kv = [&](int c, int buf) {
        const int k0 = c * 64;
#pragma unroll
        for (int j = 0; j < 10; j++) {
            int idx = j * 256 + tid;
            if (idx < 1536) {
                int r = idx / 24, cc = (idx % 24) * 8;
                cpa16(sb + SK_OFF + (uint32_t)buf * SK_SZ + ((uint32_t)r * KPAD + cc) * 2,
                      Kb + (size_t)(k0 + r) * DQK + cc);
            } else {
                int i2 = idx - 1536;
                int d = i2 / 8, cc = (i2 % 8) * 8;
                cpa16(sb + SV_OFF + (uint32_t)buf * SV_SZ + ((uint32_t)d * VPAD + cc) * 2,
                      Vb + (size_t)d * SEQ + k0 + cc);
            }
        }
    };

    issue_kv(0, 0);
    cpa_commit();
    if (nc > 1) issue_kv(1, 1);
    cpa_commit();

    float O[16][4];
#pragma unroll
    for (int dt = 0; dt < 16; dt++)
#pragma unroll
        for (int i = 0; i < 4; i++) O[dt][i] = 0.f;
    float m0 = -1e30f, m1 = -1e30f, l0 = 0.f, l1 = 0.f;

    const int row0 = q0 + wid * 16 + grp;
    const int row1 = row0 + 8;

    for (int c = 0; c < nc; ++c) {
        cpa_wait<1>();
        __syncthreads();
        const int buf = c & 1;
        const uint32_t kbase = sb + SK_OFF + (uint32_t)buf * SK_SZ;
        const uint32_t vbase = sb + SV_OFF + (uint32_t)buf * SV_SZ;
        const int k0 = c * 64;

        float S[8][4];
#pragma unroll
        for (int nt = 0; nt < 8; nt++)
#pragma unroll
            for (int i = 0; i < 4; i++) S[nt][i] = 0.f;

#pragma unroll
        for (int s16 = 0; s16 < DQK; s16 += 16) {
            uint32_t ah[4], al[4];
            uint32_t aaddr = sb + (((uint32_t)(wid * 16 + (lane & 15))) * QPAD
                                   + s16 + ((lane >> 4) << 3)) * 2;
            ldm4(ah, aaddr + SQH_OFF);
            ldm4(al, aaddr + SQL_OFF);
#pragma unroll
            for (int p = 0; p < 4; p++) {
                const int g = lane >> 3;
                uint32_t baddr = kbase +
                    (((uint32_t)(p * 16 + (lane & 7) + ((g >> 1) << 3))) * KPAD
                     + s16 + ((g & 1) << 3)) * 2;
                uint32_t bh[4];
                ldm4(bh, baddr);
                mma_f16(S[2*p],   ah, bh[0], bh[1]);
                mma_f16(S[2*p],   al, bh[0], bh[1]);
                mma_f16(S[2*p+1], ah, bh[2], bh[3]);
                mma_f16(S[2*p+1], al, bh[2], bh[3]);
            }
        }

#pragma unroll
        for (int nt = 0; nt < 8; nt++)
#pragma unroll
            for (int i = 0; i < 4; i++) S[nt][i] *= scale;
        if (c >= nc - 2) {
#pragma unroll
            for (int nt = 0; nt < 8; nt++) {
                int col = k0 + (nt >> 1) * 16 + (nt & 1) * 8 + tig * 2;
                if (col     > row0) S[nt][0] = -1e30f;
                if (col + 1 > row0) S[nt][1] = -1e30f;
                if (col     > row1) S[nt][2] = -1e30f;
                if (col + 1 > row1) S[nt][3] = -1e30f;
            }
        }

        float cm0 = -1e30f, cm1 = -1e30f;
#pragma unroll
        for (int nt = 0; nt < 8; nt++) {
            cm0 = fmaxf(cm0, fmaxf(S[nt][0], S[nt][1]));
            cm1 = fmaxf(cm1, fmaxf(S[nt][2], S[nt][3]));
        }
        cm0 = fmaxf(cm0, __shfl_xor_sync(0xffffffff, cm0, 1));
        cm0 = fmaxf(cm0, __shfl_xor_sync(0xffffffff, cm0, 2));
        cm1 = fmaxf(cm1, __shfl_xor_sync(0xffffffff, cm1, 1));
        cm1 = fmaxf(cm1, __shfl_xor_sync(0xffffffff, cm1, 2));
        float mn0 = fmaxf(m0, cm0), mn1 = fmaxf(m1, cm1);
        float a0 = __expf(m0 - mn0), a1 = __expf(m1 - mn1);
        m0 = mn0; m1 = mn1;

        float rs0 = 0.f, rs1 = 0.f;
#pragma unroll
        for (int nt = 0; nt < 8; nt++) {
            S[nt][0] = __expf(S[nt][0] - mn0);
            S[nt][1] = __expf(S[nt][1] - mn0);
            S[nt][2] = __expf(S[nt][2] - mn1);
            S[nt][3] = __expf(S[nt][3] - mn1);
            rs0 += S[nt][0] + S[nt][1];
            rs1 += S[nt][2] + S[nt][3];
        }
        rs0 += __shfl_xor_sync(0xffffffff, rs0, 1);
        rs0 += __shfl_xor_sync(0xffffffff, rs0, 2);
        rs1 += __shfl_xor_sync(0xffffffff, rs1, 1);
        rs1 += __shfl_xor_sync(0xffffffff, rs1, 2);
        l0 = l0 * a0 + rs0;
        l1 = l1 * a1 + rs1;

#pragma unroll
        for (int dt = 0; dt < 16; dt++) {
            O[dt][0] *= a0; O[dt][1] *= a0;
            O[dt][2] *= a1; O[dt][3] *= a1;
        }

#pragma unroll
        for (int kk = 0; kk < 4; kk++) {
            uint32_t pah[4], pal[4];
            half p0h, p0l, p1h, p1l;
            hsplit(S[2*kk][0], p0h, p0l);  hsplit(S[2*kk][1], p1h, p1l);
            pah[0] = pk(p0h, p1h); pal[0] = pk(p0l, p1l);
            hsplit(S[2*kk][2], p0h, p0l);  hsplit(S[2*kk][3], p1h, p1l);
            pah[1] = pk(p0h, p1h); pal[1] = pk(p0l, p1l);
            hsplit(S[2*kk+1][0], p0h, p0l); hsplit(S[2*kk+1][1], p1h, p1l);
            pah[2] = pk(p0h, p1h); pal[2] = pk(p0l, p1l);
            hsplit(S[2*kk+1][2], p0h, p0l); hsplit(S[2*kk+1][3], p1h, p1l);
            pah[3] = pk(p0h, p1h); pal[3] = pk(p0l, p1l);
#pragma unroll
            for (int p2 = 0; p2 < 8; p2++) {
                const int g = lane >> 3;
                uint32_t baddr = vbase +
                    (((uint32_t)(p2 * 16 + (lane & 7) + ((g >> 1) << 3))) * VPAD
                     + kk * 16 + ((g & 1) << 3)) * 2;
                uint32_t bv[4];
                ldm4(bv, baddr);
                mma_f16(O[2*p2],   pah, bv[0], bv[1]);
                mma_f16(O[2*p2],   pal, bv[0], bv[1]);
                mma_f16(O[2*p2+1], pah, bv[2], bv[3]);
                mma_f16(O[2*p2+1], pal, bv[2], bv[3]);
            }
        }

        __syncthreads();
        if (c + 2 < nc) issue_kv(c + 2, buf);
        cpa_commit();
    }

    const float i0 = 1.f / l0, i1 = 1.f / l1;
#pragma unroll
    for (int dt = 0; dt < 16; dt++) {
        int d = dt * 8 + tig * 2;
        half h0, lo0, h1, lo1;
        hsplit(O[dt][0] * i0, h0, lo0);
        hsplit(O[dt][1] * i0, h1, lo1);
        size_t o0 = (size_t)row0 * (NH * DV) + h * DV + d;
        *(uint32_t*)&AOh[o0] = pk(h0, h1);
        *(uint32_t*)&AOl[o0] = pk(lo0, lo1);
        hsplit(O[dt][2] * i1, h0, lo0);
        hsplit(O[dt][3] * i1, h1, lo1);
        size_t o1 = (size_t)row1 * (NH * DV) + h * DV + d;
        *(uint32_t*)&AOh[o1] = pk(h0, h1);
        *(uint32_t*)&AOl[o1] = pk(lo0, lo1);
    }
}

// ---------------- elementwise fp32 -> fp16 hi/lo split ----------------
__global__ __launch_bounds__(256)
void split_pair(const float* __restrict__ X, half* __restrict__ H,
                half* __restrict__ L, int n) {
    int i = (blockIdx.x * 256 + threadIdx.x) * 4;
    if (i >= n) return;
    float4 v = *(const float4*)&X[i];
    half h0,l0,h1,l1,h2,l2,h3,l3;
    hsplit(v.x,h0,l0); hsplit(v.y,h1,l1); hsplit(v.z,h2,l2); hsplit(v.w,h3,l3);
    *(uint2*)&H[i] = make_uint2(pk(h0,h1), pk(h2,h3));
    *(uint2*)&L[i] = make_uint2(pk(l0,l1), pk(l2,l3));
}

// -------- weight transpose: W[K,N] -> T[(rowoff+n)*K + k] fp16 --------
__global__ __launch_bounds__(256)
void wsplitT(const float* __restrict__ W, half* __restrict__ T,
             int K, int N, int rowoff) {
    __shared__ float t[32][33];
    const int n0 = blockIdx.x * 32, k0 = blockIdx.y * 32;
    const int tx = threadIdx.x & 31, ty = threadIdx.x >> 5;
#pragma unroll
    for (int i = 0; i < 4; i++) {
        int k = k0 + ty + i * 8, n = n0 + tx;
        t[ty + i * 8][tx] = (n < N) ? W[(size_t)k * N + n] : 0.f;
    }
    __syncthreads();
#pragma unroll
    for (int i = 0; i < 4; i++) {
        int n = n0 + ty + i * 8, k = k0 + tx;
        T[(size_t)(rowoff + n) * K + k] = __float2half_rn(t[tx][ty + i * 8]);
    }
}

// ---------------- rms norm -> fp16 hi/lo ----------------
__global__ __launch_bounds__(256)
void rmsnorm_split(const float* __restrict__ X, half* __restrict__ Yh,
                   half* __restrict__ Yl, const float* __restrict__ W,
                   int n, int ldx, int ldy) {
    const int r = blockIdx.x;
    const float* x = X + (size_t)r * ldx;
    const int tid = threadIdx.x;
    __shared__ float red[256];

    float ss = 0.f;
    for (int j = tid; j < n; j += 256) { float v = x[j]; ss += v * v; }
    red[tid] = ss; __syncthreads();
    for (int s = 128; s > 0; s >>= 1) {
        if (tid < s) red[tid] += red[tid + s];
        __syncthreads();
    }
    const float rinv = rsqrtf(red[0] / (float)n + 1e-6f);
    for (int j = tid; j < n; j += 256) {
        half h, l;
        hsplit(x[j] * rinv * W[j], h, l);
        Yh[(size_t)r * ldy + j] = h;
        Yl[(size_t)r * ldy + j] = l;
    }
}

// ---------------- RoPE + head gather -> fp16 (Q split; K,V single) ----------------
__global__ __launch_bounds__(256)
void rope_gather_split(const float* __restrict__ q,
                       const float* __restrict__ kv,
                       const float* __restrict__ ckv, int ldckv,
                       const float* __restrict__ cosT, const float* __restrict__ sinT,
                       const int* __restrict__ pos,
                       half* __restrict__ qfh, half* __restrict__ qfl,
                       half* __restrict__ kk, half* __restrict__ vt) {
    const int s = blockIdx.x;
    const int p = pos[s];
    const float* c  = cosT + (size_t)p * DROPE;
    const float* sn = sinT + (size_t)p * DROPE;

    for (int i = threadIdx.x; i < NH * DQK; i += 256) {
        int h = i / DQK, d = i % DQK;
        const float* qr = q + (size_t)s * NH * DQK + h * DQK;
        float val;
        if (d < DNOPE) val = qr[d];
        else {
            int dr = d - DNOPE;
            float x  = qr[d];
            float rh = (dr < DROPE / 2) ? -qr[DNOPE + dr + DROPE / 2]
                                        :  qr[DNOPE + dr - DROPE / 2];
            val = x * c[dr] + rh * sn[dr];
        }
        half hh, ll;
        hsplit(val, hh, ll);
        size_t o = ((size_t)h * SEQ + s) * DQK + d;
        qfh[o] = hh; qfl[o] = ll;
    }
    for (int i = threadIdx.x; i < NKV * DQK; i += 256) {
        int kh2 = i / DQK, d = i % DQK;
        float val;
        if (d < DNOPE) val = kv[(size_t)s * NKV * (DNOPE + DV) + kh2 * (DNOPE + DV) + d];
        else {
            int dr = d - DNOPE;
            const float* kr = ckv + (size_t)s * ldckv + KVRANK;
            float x  = kr[dr];
            float rh = (dr < DROPE / 2) ? -kr[dr + DROPE / 2] : kr[dr - DROPE / 2];
            val = x * c[dr] + rh * sn[dr];
        }
        kk[((size_t)kh2 * SEQ + s) * DQK + d] = __float2half_rn(val);
    }
    for (int i = threadIdx.x; i < NKV * DV; i += 256) {
        int kh2 = i / DV, d = i % DV;
        float val = kv[(size_t)s * NKV * (DNOPE + DV) + kh2 * (DNOPE + DV) + DNOPE + d];
        vt[((size_t)kh2 * DV + d) * SEQ + s] = __float2half_rn(val);
    }
}

// ---------------- launch ----------------
extern "C" void kernel_launch(void* const* d_in, const int* in_sizes, int n_in,
                              void* d_out, int out_size) {
    const float* hidden    = (const float*)d_in[0];
    const float* cosT      = (const float*)d_in[1];
    const float* sinT      = (const float*)d_in[2];
    const float* wq_a      = (const float*)d_in[3];
    const float* q_a_ln_w  = (const float*)d_in[4];
    const float* wq_b      = (const float*)d_in[5];
    const float* wkv_a     = (const float*)d_in[6];
    const float* kv_a_ln_w = (const float*)d_in[7];
    const float* wkv_b     = (const float*)d_in[8];
    const float* wo        = (const float*)d_in[9];
    const int*   cpos      = (const int*)d_in[10];
    float* out = (float*)d_out;

    float *qackv, *q, *kv;
    half *hidh, *hidl, *qanh, *qanl, *ckvnh, *ckvnl, *qfh, *qfl, *kk, *vt;
    half *aoh, *aol;
    half *wcombT, *wqbT, *wkvbT, *woT;

    cudaGetSymbolAddress((void**)&qackv, g_qackv);
    cudaGetSymbolAddress((void**)&q,     g_q);
    cudaGetSymbolAddress((void**)&kv,    g_kv);
    cudaGetSymbolAddress((void**)&hidh,  g_hid_h);  cudaGetSymbolAddress((void**)&hidl,  g_hid_l);
    cudaGetSymbolAddress((void**)&qanh,  g_qan_h);  cudaGetSymbolAddress((void**)&qanl,  g_qan_l);
    cudaGetSymbolAddress((void**)&ckvnh, g_ckvn_h); cudaGetSymbolAddress((void**)&ckvnl, g_ckvn_l);
    cudaGetSymbolAddress((void**)&qfh,   g_qf_h);   cudaGetSymbolAddress((void**)&qfl,   g_qf_l);
    cudaGetSymbolAddress((void**)&kk,    g_k);
    cudaGetSymbolAddress((void**)&vt,    g_vT);
    cudaGetSymbolAddress((void**)&aoh,   g_ao_h);   cudaGetSymbolAddress((void**)&aol,   g_ao_l);
    cudaGetSymbolAddress((void**)&wcombT,g_wcombT);
    cudaGetSymbolAddress((void**)&wqbT,  g_wqbT);
    cudaGetSymbolAddress((void**)&wkvbT, g_wkvbT);
    cudaGetSymbolAddress((void**)&woT,   g_woT);

    cudaFuncSetAttribute(ntgemm<false>,
        cudaFuncAttributeMaxDynamicSharedMemorySize, DSMEM);
    cudaFuncSetAttribute(ntgemm<true>,
        cudaFuncAttributeMaxDynamicSharedMemorySize, DSMEM);
    cudaFuncSetAttribute(flash_attn,
        cudaFuncAttributeMaxDynamicSharedMemorySize, FA_SMEM);

    // 0) operand conversion
    split_pair<<<SEQ*DM/1024, 256>>>(hidden, hidh, hidl, SEQ*DM);
    wsplitT<<<dim3(QRANK/32, DM/32), 256>>>(wq_a,  wcombT, DM, QRANK, 0);
    wsplitT<<<dim3(18, DM/32), 256>>>(wkv_a, wcombT, DM, KVRANK+DROPE, QRANK);
    wsplitT<<<dim3(NH*DQK/32, QRANK/32), 256>>>(wq_b, wqbT, QRANK, NH*DQK, 0);
    wsplitT<<<dim3(NKV*(DNOPE+DV)/32, KVRANK/32), 256>>>(wkv_b, wkvbT, KVRANK, NKV*(DNOPE+DV), 0);
    wsplitT<<<dim3(DM/32, NH*DV/32), 256>>>(wo, woT, NH*DV, DM, 0);

    // 1) [q_a | ckv] = hidden @ [wq_a | wkv_a]   (fused, single 92%-fill wave)
    ntgemm<true><<<dim3(NCOMB/128, SEQ/128), 256, DSMEM>>>(
        hidh, hidl, wcombT, qackv, NVALID, DM, DM, DM, NCOMB);
    // 2) rmsnorms -> fp16 splits
    rmsnorm_split<<<SEQ, 256>>>(qackv, qanh, qanl, q_a_ln_w, QRANK, NCOMB, QRANK);
    rmsnorm_split<<<SEQ, 256>>>(qackv + QRANK, ckvnh, ckvnl, kv_a_ln_w,
                                KVRANK, NCOMB, KVRANK);
    // 3) q = qan @ wq_b
    ntgemm<false><<<dim3(NH*DQK/128, SEQ/128), 256, DSMEM>>>(
        qanh, qanl, wqbT, q, NH*DQK, QRANK, QRANK, QRANK, NH*DQK);
    // 4) kv = ckvn @ wkv_b
    ntgemm<false><<<dim3(NKV*(DNOPE+DV)/128, SEQ/128), 256, DSMEM>>>(
        ckvnh, ckvnl, wkvbT, kv, NKV*(DNOPE+DV), KVRANK, KVRANK, KVRANK, NKV*(DNOPE+DV));
    // 5) RoPE + gather -> fp16 (Q split; K,V single; V transposed)
    rope_gather_split<<<SEQ, 256>>>(q, kv, qackv + QRANK, NCOMB,
                                    cosT, sinT, cpos, qfh, qfl, kk, vt);
    // 6) fused flash attention -> ao hi/lo (heavy q-tiles first)
    flash_attn<<<dim3(SEQ/128, NH), 256, FA_SMEM>>>(
        qfh, qfl, kk, vt, aoh, aol, rsqrtf((float)DQK));
    // 7) out = ao @ wo
    ntgemm<false><<<dim3(DM/128, SEQ/128), 256, DSMEM>>>(
        aoh, aol, woT, out, DM, NH*DV, NH*DV, NH*DV, DM);
}

// round 16
// speedup vs baseline: 1.6780x; 1.0453x over previous
#include <cuda_runtime.h>
#include <cuda_fp16.h>
#include <math.h>
#include <stdint.h>

#define SEQ   2048
#define NH    16
#define NKV   4
#define DQK   192
#define DNOPE 128
#define DROPE 64
#define DV    128
#define DM    2048
#define QRANK 1536
#define KVRANK 512
#define NCOMB 2176        // QRANK + 640 (kv_a width padded 576->640)
#define NVALID 2112       // QRANK + 576

// ---------------- scratch (static device globals; allocation-free) ----------------
__device__ float g_qackv[SEQ * NCOMB];     // cols 0..1535 = q_a, 1536..2111 = ckv
__device__ float g_q    [SEQ * NH * DQK];
__device__ float g_kv   [SEQ * NKV * (DNOPE + DV)];

__device__ half g_hid_h [SEQ * DM],       g_hid_l [SEQ * DM];
__device__ half g_qan_h [SEQ * QRANK],    g_qan_l [SEQ * QRANK];
__device__ half g_ckvn_h[SEQ * KVRANK],   g_ckvn_l[SEQ * KVRANK];
__device__ half g_qf_h  [NH * SEQ * DQK], g_qf_l  [NH * SEQ * DQK];
__device__ half g_k     [NKV * SEQ * DQK];
__device__ half g_vT    [NKV * DV * SEQ];
__device__ half g_ao_h  [SEQ * NH * DV],  g_ao_l  [SEQ * NH * DV];
__device__ half g_wcombT[NCOMB * DM];              // rows 0..1535 wq_a^T, 1536.. wkv_a^T
__device__ half g_wqbT [NH * DQK * QRANK];
__device__ half g_wkvbT[NKV*(DNOPE+DV)*KVRANK];
__device__ half g_woT  [DM * NH * DV];

// ---------------- helpers ----------------
__device__ __forceinline__ uint32_t s2u(const void* p) {
    uint32_t a;
    asm("{ .reg .u64 t; cvta.to.shared.u64 t, %1; cvt.u32.u64 %0, t; }"
        : "=r"(a) : "l"(p));
    return a;
}
__device__ __forceinline__ uint32_t pk(half a, half b) {
    unsigned short ua = *(unsigned short*)&a, ub = *(unsigned short*)&b;
    return (uint32_t)ua | ((uint32_t)ub << 16);
}
__device__ __forceinline__ void hsplit(float x, half& h, half& l) {
    h = __float2half_rn(x);
    l = __float2half_rn(x - __half2float(h));
}
__device__ __forceinline__ void ldm4(uint32_t* r, uint32_t addr) {
    asm volatile("ldmatrix.sync.aligned.m8n8.x4.shared.b16 {%0,%1,%2,%3}, [%4];"
        : "=r"(r[0]), "=r"(r[1]), "=r"(r[2]), "=r"(r[3]) : "r"(addr));
}
__device__ __forceinline__ void mma_f16(float* c, const uint32_t* a,
                                        uint32_t b0, uint32_t b1) {
    asm volatile("mma.sync.aligned.m16n8k16.row.col.f32.f16.f16.f32 "
        "{%0,%1,%2,%3}, {%4,%5,%6,%7}, {%8,%9}, {%0,%1,%2,%3};\n"
        : "+f"(c[0]), "+f"(c[1]), "+f"(c[2]), "+f"(c[3])
        : "r"(a[0]), "r"(a[1]), "r"(a[2]), "r"(a[3]), "r"(b0), "r"(b1));
}
__device__ __forceinline__ void cpa16(uint32_t d, const void* g) {
    asm volatile("cp.async.cg.shared.global [%0], [%1], 16;" :: "r"(d), "l"(g));
}
__device__ __forceinline__ void cpa_commit() {
    asm volatile("cp.async.commit_group;" ::: "memory");
}
template<int n>
__device__ __forceinline__ void cpa_wait() {
    asm volatile("cp.async.wait_group %0;" :: "n"(n) : "memory");
}

// ====== fp16 hi/lo 2-pass NT GEMM, 128x128x32, cp.async 3-stage ring ==========
#define SPAD   40
#define TILEB  10240
#define STAGEB 30720
#define OFF_AL 10240
#define OFF_B  20480
#define DSMEM  (3 * STAGEB)

template<bool NG>
__global__ __launch_bounds__(256, 2)
void ntgemm(const half* __restrict__ Ah, const half* __restrict__ Al,
            const half* __restrict__ B, float* __restrict__ C,
            int N, int K, int lda, int ldb, int ldc) {
    extern __shared__ __align__(16) char smem[];

    const int row0 = blockIdx.y * 128;
    const int col0 = blockIdx.x * 128;
    const int iters = K >> 5;

    const int tid = threadIdx.x, lane = tid & 31, wid = tid >> 5;
    const uint32_t sb = s2u(smem);

    const int wm = (wid & 3) * 32;
    const int wn = (wid >> 2) * 64;

    auto issue = [&](int k0, int buf) {
#pragma unroll
        for (int j = 0; j < 6; j++) {
            int i  = j * 256 + tid;
            int t  = i >> 9;
            int r  = (i >> 2) & 127;
            int qu = i & 3;
            const half* gp;
            if (t == 0)      gp = Ah + (size_t)(row0 + r) * lda + k0 + qu * 8;
            else if (t == 1) gp = Al + (size_t)(row0 + r) * lda + k0 + qu * 8;
            else             gp = B  + (size_t)(col0 + r) * ldb + k0 + qu * 8;
            uint32_t d = sb + (uint32_t)buf * STAGEB + (uint32_t)t * TILEB
                         + ((uint32_t)r * SPAD + qu * 8) * 2;
            cpa16(d, gp);
        }
    };

    float acc[2][8][4];
#pragma unroll
    for (int mt = 0; mt < 2; mt++)
#pragma unroll
        for (int nt = 0; nt < 8; nt++)
#pragma unroll
            for (int i = 0; i < 4; i++) acc[mt][nt][i] = 0.f;

    auto compute = [&](int buf) {
        const uint32_t ba = sb + (uint32_t)buf * STAGEB;
#pragma unroll
        for (int s16 = 0; s16 < 32; s16 += 16) {
            uint32_t ah[2][4], al[2][4];
#pragma unroll
            for (int mt = 0; mt < 2; mt++) {
                uint32_t addr = ba + (((uint32_t)(wm + mt * 16 + (lane & 15))) * SPAD
                                      + s16 + ((lane >> 4) << 3)) * 2;
                ldm4(ah[mt], addr);
                ldm4(al[mt], addr + OFF_AL);
            }
#pragma unroll
            for (int p = 0; p < 4; p++) {
                const int g = lane >> 3;
                uint32_t addr = ba + OFF_B +
                    (((uint32_t)(wn + p * 16 + (lane & 7) + ((g >> 1) << 3))) * SPAD
                     + s16 + ((g & 1) << 3)) * 2;
                uint32_t bh[4];
                ldm4(bh, addr);
#pragma unroll
                for (int mt = 0; mt < 2; mt++) {
                    mma_f16(acc[mt][2*p],   ah[mt], bh[0], bh[1]);
                    mma_f16(acc[mt][2*p],   al[mt], bh[0], bh[1]);
                    mma_f16(acc[mt][2*p+1], ah[mt], bh[2], bh[3]);
                    mma_f16(acc[mt][2*p+1], al[mt], bh[2], bh[3]);
                }
            }
        }
    };

    // 3-stage ring: one sync per iteration, issue before compute
    issue(0, 0);
    cpa_commit();
    if (iters > 1) issue(32, 1);
    cpa_commit();

    int mod = 0;                  // it % 3
    int mod2 = 2;                 // (it+2) % 3
    for (int it = 0; it < iters; ++it) {
        cpa_wait<1>();
        __syncthreads();
        if (it + 2 < iters) issue((it + 2) << 5, mod2);
        cpa_commit();
        compute(mod);
        mod  = (mod  == 2) ? 0 : mod  + 1;
        mod2 = (mod2 == 2) ? 0 : mod2 + 1;
    }

    const int grp = lane >> 2, tig = lane & 3;
#pragma unroll
    for (int mt = 0; mt < 2; mt++) {
#pragma unroll
        for (int nt = 0; nt < 8; nt++) {
            int r = row0 + wm + mt * 16 + grp;
            int c = col0 + wn + nt * 8 + 2 * tig;
            if (NG && c >= N) continue;
            *(float2*)&C[(size_t)r * ldc + c] =
                make_float2(acc[mt][nt][0], acc[mt][nt][1]);
            *(float2*)&C[(size_t)(r + 8) * ldc + c] =
                make_float2(acc[mt][nt][2], acc[mt][nt][3]);
        }
    }
}

// ================= fused flash attention (paired q-tiles, balanced) ===========
#define QPAD 200
#define KPAD 200
#define VPAD 72
#define SQH_OFF 0
#define SQL_OFF 51200
#define SK_OFF  102400
#define SK_SZ   25600
#define SV_OFF  153600
#define SV_SZ   18432
#define FA_SMEM 190464

__global__ __launch_bounds__(256, 1)
void flash_attn(const half* __restrict__ Qh, const half* __restrict__ Ql,
                const half* __restrict__ K, const half* __restrict__ VT,
                half* __restrict__ AOh, half* __restrict__ AOl, float scale) {
    extern __shared__ __align__(16) char smem[];
    const int h = blockIdx.y;
    const int kh = h >> 2;

    const int tid = threadIdx.x, lane = tid & 31, wid = tid >> 5;
    const int grp = lane >> 2, tig = lane & 3;
    const uint32_t sb = s2u(smem);

    const half* Kb = K  + (size_t)kh * SEQ * DQK;
    const half* Vb = VT + (size_t)kh * DV * SEQ;

    // each CTA handles q-tiles {15 - bx, bx}: (2qt+2) sums to 36 chunks, balanced
    for (int half_i = 0; half_i < 2; ++half_i) {
        const int qt = half_i == 0 ? (15 - (int)blockIdx.x) : (int)blockIdx.x;
        const int q0 = qt * 128;
        const int nc = 2 * qt + 2;

        const half* Qhb = Qh + ((size_t)h * SEQ + q0) * DQK;
        const half* Qlb = Ql + ((size_t)h * SEQ + q0) * DQK;

        // ---- issue Q tile (hi+lo) ----
#pragma unroll
        for (int j = 0; j < 24; j++) {
            int idx = j * 256 + tid;
            int t   = idx / 3072;
            int rem = idx - t * 3072;
            int r   = rem / 24;
            int cc  = (rem % 24) * 8;
            const half* src = (t ? Qlb : Qhb) + (size_t)r * DQK + cc;
            uint32_t dst = sb + (t ? SQL_OFF : SQH_OFF) + ((uint32_t)r * QPAD + cc) * 2;
            cpa16(dst, src);
        }

        auto issue_kv = [&](int c, int buf) {
            const int k0 = c * 64;
#pragma unroll
            for (int j = 0; j < 10; j++) {
                int idx = j * 256 + tid;
                if (idx < 1536) {
                    int r = idx / 24, cc = (idx % 24) * 8;
                    cpa16(sb + SK_OFF + (uint32_t)buf * SK_SZ + ((uint32_t)r * KPAD + cc) * 2,
                          Kb + (size_t)(k0 + r) * DQK + cc);
                } else {
                    int i2 = idx - 1536;
                    int d = i2 / 8, cc = (i2 % 8) * 8;
                    cpa16(sb + SV_OFF + (uint32_t)buf * SV_SZ + ((uint32_t)d * VPAD + cc) * 2,
                          Vb + (size_t)d * SEQ + k0 + cc);
                }
            }
        };

        issue_kv(0, 0);
        cpa_commit();
        if (nc > 1) issue_kv(1, 1);
        cpa_commit();

        float O[16][4];
#pragma unroll
        for (int dt = 0; dt < 16; dt++)
#pragma unroll
            for (int i = 0; i < 4; i++) O[dt][i] = 0.f;
        float m0 = -1e30f, m1 = -1e30f, l0 = 0.f, l1 = 0.f;

        const int row0 = q0 + wid * 16 + grp;
        const int row1 = row0 + 8;

        for (int c = 0; c < nc; ++c) {
            cpa_wait<1>();
            __syncthreads();
            const int buf = c & 1;
            const uint32_t kbase = sb + SK_OFF + (uint32_t)buf * SK_SZ;
            const uint32_t vbase = sb + SV_OFF + (uint32_t)buf * SV_SZ;
            const int k0 = c * 64;

            float S[8][4];
#pragma unroll
            for (int nt = 0; nt < 8; nt++)
#pragma unroll
                for (int i = 0; i < 4; i++) S[nt][i] = 0.f;

#pragma unroll
            for (int s16 = 0; s16 < DQK; s16 += 16) {
                uint32_t ah[4], al[4];
                uint32_t aaddr = sb + (((uint32_t)(wid * 16 + (lane & 15))) * QPAD
                                       + s16 + ((lane >> 4) << 3)) * 2;
                ldm4(ah, aaddr + SQH_OFF);
                ldm4(al, aaddr + SQL_OFF);
#pragma unroll
                for (int p = 0; p < 4; p++) {
                    const int g = lane >> 3;
                    uint32_t baddr = kbase +
                        (((uint32_t)(p * 16 + (lane & 7) + ((g >> 1) << 3))) * KPAD
                         + s16 + ((g & 1) << 3)) * 2;
                    uint32_t bh[4];
                    ldm4(bh, baddr);
                    mma_f16(S[2*p],   ah, bh[0], bh[1]);
                    mma_f16(S[2*p],   al, bh[0], bh[1]);
                    mma_f16(S[2*p+1], ah, bh[2], bh[3]);
                    mma_f16(S[2*p+1], al, bh[2], bh[3]);
                }
            }

#pragma unroll
            for (int nt = 0; nt < 8; nt++)
#pragma unroll
                for (int i = 0; i < 4; i++) S[nt][i] *= scale;
            if (c >= nc - 2) {
#pragma unroll
                for (int nt = 0; nt < 8; nt++) {
                    int col = k0 + (nt >> 1) * 16 + (nt & 1) * 8 + tig * 2;
                    if (col     > row0) S[nt][0] = -1e30f;
                    if (col + 1 > row0) S[nt][1] = -1e30f;
                    if (col     > row1) S[nt][2] = -1e30f;
                    if (col + 1 > row1) S[nt][3] = -1e30f;
                }
            }

            float cm0 = -1e30f, cm1 = -1e30f;
#pragma unroll
            for (int nt = 0; nt < 8; nt++) {
                cm0 = fmaxf(cm0, fmaxf(S[nt][0], S[nt][1]));
                cm1 = fmaxf(cm1, fmaxf(S[nt][2], S[nt][3]));
            }
            cm0 = fmaxf(cm0, __shfl_xor_sync(0xffffffff, cm0, 1));
            cm0 = fmaxf(cm0, __shfl_xor_sync(0xffffffff, cm0, 2));
            cm1 = fmaxf(cm1, __shfl_xor_sync(0xffffffff, cm1, 1));
            cm1 = fmaxf(cm1, __shfl_xor_sync(0xffffffff, cm1, 2));
            float mn0 = fmaxf(m0, cm0), mn1 = fmaxf(m1, cm1);
            float a0 = __expf(m0 - mn0), a1 = __expf(m1 - mn1);
            m0 = mn0; m1 = mn1;

            float rs0 = 0.f, rs1 = 0.f;
#pragma unroll
            for (int nt = 0; nt < 8; nt++) {
                S[nt][0] = __expf(S[nt][0] - mn0);
                S[nt][1] = __expf(S[nt][1] - mn0);
                S[nt][2] = __expf(S[nt][2] - mn1);
                S[nt][3] = __expf(S[nt][3] - mn1);
                rs0 += S[nt][0] + S[nt][1];
                rs1 += S[nt][2] + S[nt][3];
            }
            rs0 += __shfl_xor_sync(0xffffffff, rs0, 1);
            rs0 += __shfl_xor_sync(0xffffffff, rs0, 2);
            rs1 += __shfl_xor_sync(0xffffffff, rs1, 1);
            rs1 += __shfl_xor_sync(0xffffffff, rs1, 2);
            l0 = l0 * a0 + rs0;
            l1 = l1 * a1 + rs1;

#pragma unroll
            for (int dt = 0; dt < 16; dt++) {
                O[dt][0] *= a0; O[dt][1] *= a0;
                O[dt][2] *= a1; O[dt][3] *= a1;
            }

#pragma unroll
            for (int kk = 0; kk < 4; kk++) {
                uint32_t pah[4], pal[4];
                half p0h, p0l, p1h, p1l;
                hsplit(S[2*kk][0], p0h, p0l);  hsplit(S[2*kk][1], p1h, p1l);
                pah[0] = pk(p0h, p1h); pal[0] = pk(p0l, p1l);
                hsplit(S[2*kk][2], p0h, p0l);  hsplit(S[2*kk][3], p1h, p1l);
                pah[1] = pk(p0h, p1h); pal[1] = pk(p0l, p1l);
                hsplit(S[2*kk+1][0], p0h, p0l); hsplit(S[2*kk+1][1], p1h, p1l);
                pah[2] = pk(p0h, p1h); pal[2] = pk(p0l, p1l);
                hsplit(S[2*kk+1][2], p0h, p0l); hsplit(S[2*kk+1][3], p1h, p1l);
                pah[3] = pk(p0h, p1h); pal[3] = pk(p0l, p1l);
#pragma unroll
                for (int p2 = 0; p2 < 8; p2++) {
                    const int g = lane >> 3;
                    uint32_t baddr = vbase +
                        (((uint32_t)(p2 * 16 + (lane & 7) + ((g >> 1) << 3))) * VPAD
                         + kk * 16 + ((g & 1) << 3)) * 2;
                    uint32_t bv[4];
                    ldm4(bv, baddr);
                    mma_f16(O[2*p2],   pah, bv[0], bv[1]);
                    mma_f16(O[2*p2],   pal, bv[0], bv[1]);
                    mma_f16(O[2*p2+1], pah, bv[2], bv[3]);
                    mma_f16(O[2*p2+1], pal, bv[2], bv[3]);
                }
            }

            __syncthreads();
            if (c + 2 < nc) issue_kv(c + 2, buf);
            cpa_commit();
        }

        const float i0 = 1.f / l0, i1 = 1.f / l1;
#pragma unroll
        for (int dt = 0; dt < 16; dt++) {
            int d = dt * 8 + tig * 2;
            half h0, lo0, h1, lo1;
            hsplit(O[dt][0] * i0, h0, lo0);
            hsplit(O[dt][1] * i0, h1, lo1);
            size_t o0 = (size_t)row0 * (NH * DV) + h * DV + d;
            *(uint32_t*)&AOh[o0] = pk(h0, h1);
            *(uint32_t*)&AOl[o0] = pk(lo0, lo1);
            hsplit(O[dt][2] * i1, h0, lo0);
            hsplit(O[dt][3] * i1, h1, lo1);
            size_t o1 = (size_t)row1 * (NH * DV) + h * DV + d;
            *(uint32_t*)&AOh[o1] = pk(h0, h1);
            *(uint32_t*)&AOl[o1] = pk(lo0, lo1);
        }
        __syncthreads();   // all threads done with smem before next half reuses it
    }
}

// ---------------- elementwise fp32 -> fp16 hi/lo split ----------------
__global__ __launch_bounds__(256)
void split_pair(const float* __restrict__ X, half* __restrict__ H,
                half* __restrict__ L, int n) {
    int i = (blockIdx.x * 256 + threadIdx.x) * 4;
    if (i >= n) return;
    float4 v = *(const float4*)&X[i];
    half h0,l0,h1,l1,h2,l2,h3,l3;
    hsplit(v.x,h0,l0); hsplit(v.y,h1,l1); hsplit(v.z,h2,l2); hsplit(v.w,h3,l3);
    *(uint2*)&H[i] = make_uint2(pk(h0,h1), pk(h2,h3));
    *(uint2*)&L[i] = make_uint2(pk(l0,l1), pk(l2,l3));
}

// -------- weight transpose: W[K,N] -> T[(rowoff+n)*K + k] fp16 --------
__global__ __launch_bounds__(256)
void wsplitT(const float* __restrict__ W, half* __restrict__ T,
             int K, int N, int rowoff) {
    __shared__ float t[32][33];
    const int n0 = blockIdx.x * 32, k0 = blockIdx.y * 32;
    const int tx = threadIdx.x & 31, ty = threadIdx.x >> 5;
#pragma unroll
    for (int i = 0; i < 4; i++) {
        int k = k0 + ty + i * 8, n = n0 + tx;
        t[ty + i * 8][tx] = (n < N) ? W[(size_t)k * N + n] : 0.f;
    }
    __syncthreads();
#pragma unroll
    for (int i = 0; i < 4; i++) {
        int n = n0 + ty + i * 8, k = k0 + tx;
        T[(size_t)(rowoff + n) * K + k] = __float2half_rn(t[tx][ty + i * 8]);
    }
}

// ---------------- rms norm -> fp16 hi/lo ----------------
__global__ __launch_bounds__(256)
void rmsnorm_split(const float* __restrict__ X, half* __restrict__ Yh,
                   half* __restrict__ Yl, const float* __restrict__ W,
                   int n, int ldx, int ldy) {
    const int r = blockIdx.x;
    const float* x = X + (size_t)r * ldx;
    const int tid = threadIdx.x;
    __shared__ float red[256];

    float ss = 0.f;
    for (int j = tid; j < n; j += 256) { float v = x[j]; ss += v * v; }
    red[tid] = ss; __syncthreads();
    for (int s = 128; s > 0; s >>= 1) {
        if (tid < s) red[tid] += red[tid + s];
        __syncthreads();
    }
    const float rinv = rsqrtf(red[0] / (float)n + 1e-6f);
    for (int j = tid; j < n; j += 256) {
        half h, l;
        hsplit(x[j] * rinv * W[j], h, l);
        Yh[(size_t)r * ldy + j] = h;
        Yl[(size_t)r * ldy + j] = l;
    }
}

// ---------------- RoPE + head gather -> fp16 (Q split; K,V single) ----------------
__global__ __launch_bounds__(256)
void rope_gather_split(const float* __restrict__ q,
                       const float* __restrict__ kv,
                       const float* __restrict__ ckv, int ldckv,
                       const float* __restrict__ cosT, const float* __restrict__ sinT,
                       const int* __restrict__ pos,
                       half* __restrict__ qfh, half* __restrict__ qfl,
                       half* __restrict__ kk, half* __restrict__ vt) {
    const int s = blockIdx.x;
    const int p = pos[s];
    const float* c  = cosT + (size_t)p * DROPE;
    const float* sn = sinT + (size_t)p * DROPE;

    for (int i = threadIdx.x; i < NH * DQK; i += 256) {
        int h = i / DQK, d = i % DQK;
        const float* qr = q + (size_t)s * NH * DQK + h * DQK;
        float val;
        if (d < DNOPE) val = qr[d];
        else {
            int dr = d - DNOPE;
            float x  = qr[d];
            float rh = (dr < DROPE / 2) ? -qr[DNOPE + dr + DROPE / 2]
                                        :  qr[DNOPE + dr - DROPE / 2];
            val = x * c[dr] + rh * sn[dr];
        }
        half hh, ll;
        hsplit(val, hh, ll);
        size_t o = ((size_t)h * SEQ + s) * DQK + d;
        qfh[o] = hh; qfl[o] = ll;
    }
    for (int i = threadIdx.x; i < NKV * DQK; i += 256) {
        int kh2 = i / DQK, d = i % DQK;
        float val;
        if (d < DNOPE) val = kv[(size_t)s * NKV * (DNOPE + DV) + kh2 * (DNOPE + DV) + d];
        else {
            int dr = d - DNOPE;
            const float* kr = ckv + (size_t)s * ldckv + KVRANK;
            float x  = kr[dr];
            float rh = (dr < DROPE / 2) ? -kr[dr + DROPE / 2] : kr[dr - DROPE / 2];
            val = x * c[dr] + rh * sn[dr];
        }
        kk[((size_t)kh2 * SEQ + s) * DQK + d] = __float2half_rn(val);
    }
    for (int i = threadIdx.x; i < NKV * DV; i += 256) {
        int kh2 = i / DV, d = i % DV;
        float val = kv[(size_t)s * NKV * (DNOPE + DV) + kh2 * (DNOPE + DV) + DNOPE + d];
        vt[((size_t)kh2 * DV + d) * SEQ + s] = __float2half_rn(val);
    }
}

// ---------------- launch ----------------
extern "C" void kernel_launch(void* const* d_in, const int* in_sizes, int n_in,
                              void* d_out, int out_size) {
    const float* hidden    = (const float*)d_in[0];
    const float* cosT      = (const float*)d_in[1];
    const float* sinT      = (const float*)d_in[2];
    const float* wq_a      = (const float*)d_in[3];
    const float* q_a_ln_w  = (const float*)d_in[4];
    const float* wq_b      = (const float*)d_in[5];
    const float* wkv_a     = (const float*)d_in[6];
    const float* kv_a_ln_w = (const float*)d_in[7];
    const float* wkv_b     = (const float*)d_in[8];
    const float* wo        = (const float*)d_in[9];
    const int*   cpos      = (const int*)d_in[10];
    float* out = (float*)d_out;

    float *qackv, *q, *kv;
    half *hidh, *hidl, *qanh, *qanl, *ckvnh, *ckvnl, *qfh, *qfl, *kk, *vt;
    half *aoh, *aol;
    half *wcombT, *wqbT, *wkvbT, *woT;

    cudaGetSymbolAddress((void**)&qackv, g_qackv);
    cudaGetSymbolAddress((void**)&q,     g_q);
    cudaGetSymbolAddress((void**)&kv,    g_kv);
    cudaGetSymbolAddress((void**)&hidh,  g_hid_h);  cudaGetSymbolAddress((void**)&hidl,  g_hid_l);
    cudaGetSymbolAddress((void**)&qanh,  g_qan_h);  cudaGetSymbolAddress((void**)&qanl,  g_qan_l);
    cudaGetSymbolAddress((void**)&ckvnh, g_ckvn_h); cudaGetSymbolAddress((void**)&ckvnl, g_ckvn_l);
    cudaGetSymbolAddress((void**)&qfh,   g_qf_h);   cudaGetSymbolAddress((void**)&qfl,   g_qf_l);
    cudaGetSymbolAddress((void**)&kk,    g_k);
    cudaGetSymbolAddress((void**)&vt,    g_vT);
    cudaGetSymbolAddress((void**)&aoh,   g_ao_h);   cudaGetSymbolAddress((void**)&aol,   g_ao_l);
    cudaGetSymbolAddress((void**)&wcombT,g_wcombT);
    cudaGetSymbolAddress((void**)&wqbT,  g_wqbT);
    cudaGetSymbolAddress((void**)&wkvbT, g_wkvbT);
    cudaGetSymbolAddress((void**)&woT,   g_woT);

    cudaFuncSetAttribute(ntgemm<false>,
        cudaFuncAttributeMaxDynamicSharedMemorySize, DSMEM);
    cudaFuncSetAttribute(ntgemm<true>,
        cudaFuncAttributeMaxDynamicSharedMemorySize, DSMEM);
    cudaFuncSetAttribute(flash_attn,
        cudaFuncAttributeMaxDynamicSharedMemorySize, FA_SMEM);

    // 0) operand conversion
    split_pair<<<SEQ*DM/1024, 256>>>(hidden, hidh, hidl, SEQ*DM);
    wsplitT<<<dim3(QRANK/32, DM/32), 256>>>(wq_a,  wcombT, DM, QRANK, 0);
    wsplitT<<<dim3(18, DM/32), 256>>>(wkv_a, wcombT, DM, KVRANK+DROPE, QRANK);
    wsplitT<<<dim3(NH*DQK/32, QRANK/32), 256>>>(wq_b, wqbT, QRANK, NH*DQK, 0);
    wsplitT<<<dim3(NKV*(DNOPE+DV)/32, KVRANK/32), 256>>>(wkv_b, wkvbT, KVRANK, NKV*(DNOPE+DV), 0);
    wsplitT<<<dim3(DM/32, NH*DV/32), 256>>>(wo, woT, NH*DV, DM, 0);

    // 1) [q_a | ckv] = hidden @ [wq_a | wkv_a]   (fused, single 92%-fill wave)
    ntgemm<true><<<dim3(NCOMB/128, SEQ/128), 256, DSMEM>>>(
        hidh, hidl, wcombT, qackv, NVALID, DM, DM, DM, NCOMB);
    // 2) rmsnorms -> fp16 splits
    rmsnorm_split<<<SEQ, 256>>>(qackv, qanh, qanl, q_a_ln_w, QRANK, NCOMB, QRANK);
    rmsnorm_split<<<SEQ, 256>>>(qackv + QRANK, ckvnh, ckvnl, kv_a_ln_w,
                                KVRANK, NCOMB, KVRANK);
    // 3) q = qan @ wq_b
    ntgemm<false><<<dim3(NH*DQK/128, SEQ/128), 256, DSMEM>>>(
        qanh, qanl, wqbT, q, NH*DQK, QRANK, QRANK, QRANK, NH*DQK);
    // 4) kv = ckvn @ wkv_b
    ntgemm<false><<<dim3(NKV*(DNOPE+DV)/128, SEQ/128), 256, DSMEM>>>(
        ckvnh, ckvnl, wkvbT, kv, NKV*(DNOPE+DV), KVRANK, KVRANK, KVRANK, NKV*(DNOPE+DV));
    // 5) RoPE + gather -> fp16 (Q split; K,V single; V transposed)
    rope_gather_split<<<SEQ, 256>>>(q, kv, qackv + QRANK, NCOMB,
                                    cosT, sinT, cpos, qfh, qfl, kk, vt);
    // 6) fused flash attention -> ao hi/lo (paired q-tiles, one balanced wave)
    flash_attn<<<dim3(8, NH), 256, FA_SMEM>>>(
        qfh, qfl, kk, vt, aoh, aol, rsqrtf((float)DQK));
    // 7) out = ao @ wo
    ntgemm<false><<<dim3(DM/128, SEQ/128), 256, DSMEM>>>(
        aoh, aol, woT, out, DM, NH*DV, NH*DV, NH*DV, DM);
}

// round 17
// speedup vs baseline: 1.9476x; 1.1607x over previous
#include <cuda_runtime.h>
#include <cuda_fp16.h>
#include <math.h>
#include <stdint.h>

#define SEQ   2048
#define NH    16
#define NKV   4
#define DQK   192
#define DNOPE 128
#define DROPE 64
#define DV    128
#define DM    2048
#define QRANK 1536
#define KVRANK 512
#define NCOMB 2176        // QRANK + 640 (kv_a width padded 576->640)
#define NVALID 2112       // QRANK + 576

// ---------------- scratch (static device globals; allocation-free) ----------------
__device__ float g_qackv[SEQ * NCOMB];     // cols 0..1535 = q_a, 1536..2111 = ckv
__device__ float g_q    [SEQ * NH * DQK];
__device__ float g_kv   [SEQ * NKV * (DNOPE + DV)];

__device__ half g_hid_h [SEQ * DM],       g_hid_l [SEQ * DM];
__device__ half g_qan_h [SEQ * QRANK],    g_qan_l [SEQ * QRANK];
__device__ half g_ckvn_h[SEQ * KVRANK],   g_ckvn_l[SEQ * KVRANK];
__device__ half g_qf_h  [NH * SEQ * DQK], g_qf_l  [NH * SEQ * DQK];
__device__ half g_k     [NKV * SEQ * DQK];
__device__ half g_vT    [NKV * DV * SEQ];
__device__ half g_ao    [SEQ * NH * DV];           // single fp16 now
__device__ half g_wcombT[NCOMB * DM];              // rows 0..1535 wq_a^T, 1536.. wkv_a^T
__device__ half g_wqbT [NH * DQK * QRANK];
__device__ half g_wkvbT[NKV*(DNOPE+DV)*KVRANK];
__device__ half g_woT  [DM * NH * DV];

// ---------------- helpers ----------------
__device__ __forceinline__ uint32_t s2u(const void* p) {
    uint32_t a;
    asm("{ .reg .u64 t; cvta.to.shared.u64 t, %1; cvt.u32.u64 %0, t; }"
        : "=r"(a) : "l"(p));
    return a;
}
__device__ __forceinline__ uint32_t pk(half a, half b) {
    unsigned short ua = *(unsigned short*)&a, ub = *(unsigned short*)&b;
    return (uint32_t)ua | ((uint32_t)ub << 16);
}
__device__ __forceinline__ void hsplit(float x, half& h, half& l) {
    h = __float2half_rn(x);
    l = __float2half_rn(x - __half2float(h));
}
__device__ __forceinline__ void ldm4(uint32_t* r, uint32_t addr) {
    asm volatile("ldmatrix.sync.aligned.m8n8.x4.shared.b16 {%0,%1,%2,%3}, [%4];"
        : "=r"(r[0]), "=r"(r[1]), "=r"(r[2]), "=r"(r[3]) : "r"(addr));
}
__device__ __forceinline__ void mma_f16(float* c, const uint32_t* a,
                                        uint32_t b0, uint32_t b1) {
    asm volatile("mma.sync.aligned.m16n8k16.row.col.f32.f16.f16.f32 "
        "{%0,%1,%2,%3}, {%4,%5,%6,%7}, {%8,%9}, {%0,%1,%2,%3};\n"
        : "+f"(c[0]), "+f"(c[1]), "+f"(c[2]), "+f"(c[3])
        : "r"(a[0]), "r"(a[1]), "r"(a[2]), "r"(a[3]), "r"(b0), "r"(b1));
}
__device__ __forceinline__ void cpa16(uint32_t d, const void* g) {
    asm volatile("cp.async.cg.shared.global [%0], [%1], 16;" :: "r"(d), "l"(g));
}
__device__ __forceinline__ void cpa_commit() {
    asm volatile("cp.async.commit_group;" ::: "memory");
}
template<int n>
__device__ __forceinline__ void cpa_wait() {
    asm volatile("cp.async.wait_group %0;" :: "n"(n) : "memory");
}

// ====== fp16 hi/lo NT GEMM, 128x128x32, cp.async 3-stage ring =================
// ONEA: A has no lo part (1-pass).
#define SPAD   40
#define TILEB  10240
#define STAGEB 30720
#define OFF_AL 10240
#define OFF_B  20480
#define DSMEM  (3 * STAGEB)

template<bool NG, bool ONEA>
__global__ __launch_bounds__(256, 2)
void ntgemm(const half* __restrict__ Ah, const half* __restrict__ Al,
            const half* __restrict__ B, float* __restrict__ C,
            int N, int K, int lda, int ldb, int ldc) {
    extern __shared__ __align__(16) char smem[];

    const int row0 = blockIdx.y * 128;
    const int col0 = blockIdx.x * 128;
    const int iters = K >> 5;

    const int tid = threadIdx.x, lane = tid & 31, wid = tid >> 5;
    const uint32_t sb = s2u(smem);

    const int wm = (wid & 3) * 32;
    const int wn = (wid >> 2) * 64;

    auto issue = [&](int k0, int buf) {
#pragma unroll
        for (int j = 0; j < 6; j++) {
            int i  = j * 256 + tid;
            int t  = i >> 9;
            if (ONEA && t == 1) continue;
            int r  = (i >> 2) & 127;
            int qu = i & 3;
            const half* gp;
            if (t == 0)      gp = Ah + (size_t)(row0 + r) * lda + k0 + qu * 8;
            else if (t == 1) gp = Al + (size_t)(row0 + r) * lda + k0 + qu * 8;
            else             gp = B  + (size_t)(col0 + r) * ldb + k0 + qu * 8;
            uint32_t d = sb + (uint32_t)buf * STAGEB + (uint32_t)t * TILEB
                         + ((uint32_t)r * SPAD + qu * 8) * 2;
            cpa16(d, gp);
        }
    };

    float acc[2][8][4];
#pragma unroll
    for (int mt = 0; mt < 2; mt++)
#pragma unroll
        for (int nt = 0; nt < 8; nt++)
#pragma unroll
            for (int i = 0; i < 4; i++) acc[mt][nt][i] = 0.f;

    auto compute = [&](int buf) {
        const uint32_t ba = sb + (uint32_t)buf * STAGEB;
#pragma unroll
        for (int s16 = 0; s16 < 32; s16 += 16) {
            uint32_t ah[2][4], al[2][4];
#pragma unroll
            for (int mt = 0; mt < 2; mt++) {
                uint32_t addr = ba + (((uint32_t)(wm + mt * 16 + (lane & 15))) * SPAD
                                      + s16 + ((lane >> 4) << 3)) * 2;
                ldm4(ah[mt], addr);
                if (!ONEA) ldm4(al[mt], addr + OFF_AL);
            }
#pragma unroll
            for (int p = 0; p < 4; p++) {
                const int g = lane >> 3;
                uint32_t addr = ba + OFF_B +
                    (((uint32_t)(wn + p * 16 + (lane & 7) + ((g >> 1) << 3))) * SPAD
                     + s16 + ((g & 1) << 3)) * 2;
                uint32_t bh[4];
                ldm4(bh, addr);
#pragma unroll
                for (int mt = 0; mt < 2; mt++) {
                    mma_f16(acc[mt][2*p],   ah[mt], bh[0], bh[1]);
                    if (!ONEA) mma_f16(acc[mt][2*p], al[mt], bh[0], bh[1]);
                    mma_f16(acc[mt][2*p+1], ah[mt], bh[2], bh[3]);
                    if (!ONEA) mma_f16(acc[mt][2*p+1], al[mt], bh[2], bh[3]);
                }
            }
        }
    };

    // 3-stage ring: one sync per iteration, issue before compute
    issue(0, 0);
    cpa_commit();
    if (iters > 1) issue(32, 1);
    cpa_commit();

    int mod = 0;
    int mod2 = 2;
    for (int it = 0; it < iters; ++it) {
        cpa_wait<1>();
        __syncthreads();
        if (it + 2 < iters) issue((it + 2) << 5, mod2);
        cpa_commit();
        compute(mod);
        mod  = (mod  == 2) ? 0 : mod  + 1;
        mod2 = (mod2 == 2) ? 0 : mod2 + 1;
    }

    const int grp = lane >> 2, tig = lane & 3;
#pragma unroll
    for (int mt = 0; mt < 2; mt++) {
#pragma unroll
        for (int nt = 0; nt < 8; nt++) {
            int r = row0 + wm + mt * 16 + grp;
            int c = col0 + wn + nt * 8 + 2 * tig;
            if (NG && c >= N) continue;
            *(float2*)&C[(size_t)r * ldc + c] =
                make_float2(acc[mt][nt][0], acc[mt][nt][1]);
            *(float2*)&C[(size_t)(r + 8) * ldc + c] =
                make_float2(acc[mt][nt][2], acc[mt][nt][3]);
        }
    }
}

// ================= fused flash attention (paired q-tiles, 1-pass PV) ==========
#define QPAD 200
#define KPAD 200
#define VPAD 72
#define SQH_OFF 0
#define SQL_OFF 51200
#define SK_OFF  102400
#define SK_SZ   25600
#define SV_OFF  153600
#define SV_SZ   18432
#define FA_SMEM 190464

__global__ __launch_bounds__(256, 1)
void flash_attn(const half* __restrict__ Qh, const half* __restrict__ Ql,
                const half* __restrict__ K, const half* __restrict__ VT,
                half* __restrict__ AO, float scale) {
    extern __shared__ __align__(16) char smem[];
    const int h = blockIdx.y;
    const int kh = h >> 2;

    const int tid = threadIdx.x, lane = tid & 31, wid = tid >> 5;
    const int grp = lane >> 2, tig = lane & 3;
    const uint32_t sb = s2u(smem);

    const half* Kb = K  + (size_t)kh * SEQ * DQK;
    const half* Vb = VT + (size_t)kh * DV * SEQ;

    // each CTA handles q-tiles {15 - bx, bx}: totals 36 chunks, balanced
    for (int half_i = 0; half_i < 2; ++half_i) {
        const int qt = half_i == 0 ? (15 - (int)blockIdx.x) : (int)blockIdx.x;
        const int q0 = qt * 128;
        const int nc = 2 * qt + 2;

        const half* Qhb = Qh + ((size_t)h * SEQ + q0) * DQK;
        const half* Qlb = Ql + ((size_t)h * SEQ + q0) * DQK;

        // ---- issue Q tile (hi+lo) ----
#pragma unroll
        for (int j = 0; j < 24; j++) {
            int idx = j * 256 + tid;
            int t   = idx / 3072;
            int rem = idx - t * 3072;
            int r   = rem / 24;
            int cc  = (rem % 24) * 8;
            const half* src = (t ? Qlb : Qhb) + (size_t)r * DQK + cc;
            uint32_t dst = sb + (t ? SQL_OFF : SQH_OFF) + ((uint32_t)r * QPAD + cc) * 2;
            cpa16(dst, src);
        }

        auto issue_kv = [&](int c, int buf) {
            const int k0 = c * 64;
#pragma unroll
            for (int j = 0; j < 10; j++) {
                int idx = j * 256 + tid;
                if (idx < 1536) {
                    int r = idx / 24, cc = (idx % 24) * 8;
                    cpa16(sb + SK_OFF + (uint32_t)buf * SK_SZ + ((uint32_t)r * KPAD + cc) * 2,
                          Kb + (size_t)(k0 + r) * DQK + cc);
                } else {
                    int i2 = idx - 1536;
                    int d = i2 / 8, cc = (i2 % 8) * 8;
                    cpa16(sb + SV_OFF + (uint32_t)buf * SV_SZ + ((uint32_t)d * VPAD + cc) * 2,
                          Vb + (size_t)d * SEQ + k0 + cc);
                }
            }
        };

        issue_kv(0, 0);
        cpa_commit();
        if (nc > 1) issue_kv(1, 1);
        cpa_commit();

        float O[16][4];
#pragma unroll
        for (int dt = 0; dt < 16; dt++)
#pragma unroll
            for (int i = 0; i < 4; i++) O[dt][i] = 0.f;
        float m0 = -1e30f, m1 = -1e30f, l0 = 0.f, l1 = 0.f;

        const int row0 = q0 + wid * 16 + grp;
        const int row1 = row0 + 8;

        for (int c = 0; c < nc; ++c) {
            cpa_wait<1>();
            __syncthreads();
            const int buf = c & 1;
            const uint32_t kbase = sb + SK_OFF + (uint32_t)buf * SK_SZ;
            const uint32_t vbase = sb + SV_OFF + (uint32_t)buf * SV_SZ;
            const int k0 = c * 64;

            float S[8][4];
#pragma unroll
            for (int nt = 0; nt < 8; nt++)
#pragma unroll
                for (int i = 0; i < 4; i++) S[nt][i] = 0.f;

#pragma unroll
            for (int s16 = 0; s16 < DQK; s16 += 16) {
                uint32_t ah[4], al[4];
                uint32_t aaddr = sb + (((uint32_t)(wid * 16 + (lane & 15))) * QPAD
                                       + s16 + ((lane >> 4) << 3)) * 2;
                ldm4(ah, aaddr + SQH_OFF);
                ldm4(al, aaddr + SQL_OFF);
#pragma unroll
                for (int p = 0; p < 4; p++) {
                    const int g = lane >> 3;
                    uint32_t baddr = kbase +
                        (((uint32_t)(p * 16 + (lane & 7) + ((g >> 1) << 3))) * KPAD
                         + s16 + ((g & 1) << 3)) * 2;
                    uint32_t bh[4];
                    ldm4(bh, baddr);
                    mma_f16(S[2*p],   ah, bh[0], bh[1]);
                    mma_f16(S[2*p],   al, bh[0], bh[1]);
                    mma_f16(S[2*p+1], ah, bh[2], bh[3]);
                    mma_f16(S[2*p+1], al, bh[2], bh[3]);
                }
            }

#pragma unroll
            for (int nt = 0; nt < 8; nt++)
#pragma unroll
                for (int i = 0; i < 4; i++) S[nt][i] *= scale;
            if (c >= nc - 2) {
#pragma unroll
                for (int nt = 0; nt < 8; nt++) {
                    int col = k0 + (nt >> 1) * 16 + (nt & 1) * 8 + tig * 2;
                    if (col     > row0) S[nt][0] = -1e30f;
                    if (col + 1 > row0) S[nt][1] = -1e30f;
                    if (col     > row1) S[nt][2] = -1e30f;
                    if (col + 1 > row1) S[nt][3] = -1e30f;
                }
            }

            float cm0 = -1e30f, cm1 = -1e30f;
#pragma unroll
            for (int nt = 0; nt < 8; nt++) {
                cm0 = fmaxf(cm0, fmaxf(S[nt][0], S[nt][1]));
                cm1 = fmaxf(cm1, fmaxf(S[nt][2], S[nt][3]));
            }
            cm0 = fmaxf(cm0, __shfl_xor_sync(0xffffffff, cm0, 1));
            cm0 = fmaxf(cm0, __shfl_xor_sync(0xffffffff, cm0, 2));
            cm1 = fmaxf(cm1, __shfl_xor_sync(0xffffffff, cm1, 1));
            cm1 = fmaxf(cm1, __shfl_xor_sync(0xffffffff, cm1, 2));
            float mn0 = fmaxf(m0, cm0), mn1 = fmaxf(m1, cm1);
            float a0 = __expf(m0 - mn0), a1 = __expf(m1 - mn1);
            m0 = mn0; m1 = mn1;

            float rs0 = 0.f, rs1 = 0.f;
#pragma unroll
            for (int nt = 0; nt < 8; nt++) {
                S[nt][0] = __expf(S[nt][0] - mn0);
                S[nt][1] = __expf(S[nt][1] - mn0);
                S[nt][2] = __expf(S[nt][2] - mn1);
                S[nt][3] = __expf(S[nt][3] - mn1);
                rs0 += S[nt][0] + S[nt][1];
                rs1 += S[nt][2] + S[nt][3];
            }
            rs0 += __shfl_xor_sync(0xffffffff, rs0, 1);
            rs0 += __shfl_xor_sync(0xffffffff, rs0, 2);
            rs1 += __shfl_xor_sync(0xffffffff, rs1, 1);
            rs1 += __shfl_xor_sync(0xffffffff, rs1, 2);
            l0 = l0 * a0 + rs0;
            l1 = l1 * a1 + rs1;

#pragma unroll
            for (int dt = 0; dt < 16; dt++) {
                O[dt][0] *= a0; O[dt][1] *= a0;
                O[dt][2] *= a1; O[dt][3] *= a1;
            }

            // ---- O += P V  (P single fp16, 1-pass) ----
#pragma unroll
            for (int kk = 0; kk < 4; kk++) {
                uint32_t pah[4];
                pah[0] = pk(__float2half_rn(S[2*kk][0]),   __float2half_rn(S[2*kk][1]));
                pah[1] = pk(__float2half_rn(S[2*kk][2]),   __float2half_rn(S[2*kk][3]));
                pah[2] = pk(__float2half_rn(S[2*kk+1][0]), __float2half_rn(S[2*kk+1][1]));
                pah[3] = pk(__float2half_rn(S[2*kk+1][2]), __float2half_rn(S[2*kk+1][3]));
#pragma unroll
                for (int p2 = 0; p2 < 8; p2++) {
                    const int g = lane >> 3;
                    uint32_t baddr = vbase +
                        (((uint32_t)(p2 * 16 + (lane & 7) + ((g >> 1) << 3))) * VPAD
                         + kk * 16 + ((g & 1) << 3)) * 2;
                    uint32_t bv[4];
                    ldm4(bv, baddr);
                    mma_f16(O[2*p2],   pah, bv[0], bv[1]);
                    mma_f16(O[2*p2+1], pah, bv[2], bv[3]);
                }
            }

            __syncthreads();
            if (c + 2 < nc) issue_kv(c + 2, buf);
            cpa_commit();
        }

        const float i0 = 1.f / l0, i1 = 1.f / l1;
#pragma unroll
        for (int dt = 0; dt < 16; dt++) {
            int d = dt * 8 + tig * 2;
            size_t o0 = (size_t)row0 * (NH * DV) + h * DV + d;
            *(uint32_t*)&AO[o0] = pk(__float2half_rn(O[dt][0] * i0),
                                     __float2half_rn(O[dt][1] * i0));
            size_t o1 = (size_t)row1 * (NH * DV) + h * DV + d;
            *(uint32_t*)&AO[o1] = pk(__float2half_rn(O[dt][2] * i1),
                                     __float2half_rn(O[dt][3] * i1));
        }
        __syncthreads();   // all threads done with smem before next half reuses it
    }
}

// ---------------- elementwise fp32 -> fp16 hi/lo split ----------------
__global__ __launch_bounds__(256)
void split_pair(const float* __restrict__ X, half* __restrict__ H,
                half* __restrict__ L, int n) {
    int i = (blockIdx.x * 256 + threadIdx.x) * 4;
    if (i >= n) return;
    float4 v = *(const float4*)&X[i];
    half h0,l0,h1,l1,h2,l2,h3,l3;
    hsplit(v.x,h0,l0); hsplit(v.y,h1,l1); hsplit(v.z,h2,l2); hsplit(v.w,h3,l3);
    *(uint2*)&H[i] = make_uint2(pk(h0,h1), pk(h2,h3));
    *(uint2*)&L[i] = make_uint2(pk(l0,l1), pk(l2,l3));
}

// -------- weight transpose: W[K,N] -> T[(rowoff+n)*K + k] fp16 --------
__global__ __launch_bounds__(256)
void wsplitT(const float* __restrict__ W, half* __restrict__ T,
             int K, int N, int rowoff) {
    __shared__ float t[32][33];
    const int n0 = blockIdx.x * 32, k0 = blockIdx.y * 32;
    const int tx = threadIdx.x & 31, ty = threadIdx.x >> 5;
#pragma unroll
    for (int i = 0; i < 4; i++) {
        int k = k0 + ty + i * 8, n = n0 + tx;
        t[ty + i * 8][tx] = (n < N) ? W[(size_t)k * N + n] : 0.f;
    }
    __syncthreads();
#pragma unroll
    for (int i = 0; i < 4; i++) {
        int n = n0 + ty + i * 8, k = k0 + tx;
        T[(size_t)(rowoff + n) * K + k] = __float2half_rn(t[tx][ty + i * 8]);
    }
}

// ---------------- rms norm -> fp16 hi/lo ----------------
__global__ __launch_bounds__(256)
void rmsnorm_split(const float* __restrict__ X, half* __restrict__ Yh,
                   half* __restrict__ Yl, const float* __restrict__ W,
                   int n, int ldx, int ldy) {
    const int r = blockIdx.x;
    const float* x = X + (size_t)r * ldx;
    const int tid = threadIdx.x;
    __shared__ float red[256];

    float ss = 0.f;
    for (int j = tid; j < n; j += 256) { float v = x[j]; ss += v * v; }
    red[tid] = ss; __syncthreads();
    for (int s = 128; s > 0; s >>= 1) {
        if (tid < s) red[tid] += red[tid + s];
        __syncthreads();
    }
    const float rinv = rsqrtf(red[0] / (float)n + 1e-6f);
    for (int j = tid; j < n; j += 256) {
        half h, l;
        hsplit(x[j] * rinv * W[j], h, l);
        Yh[(size_t)r * ldy + j] = h;
        Yl[(size_t)r * ldy + j] = l;
    }
}

// ---------------- RoPE + head gather -> fp16 (Q split; K,V single) ----------------
__global__ __launch_bounds__(256)
void rope_gather_split(const float* __restrict__ q,
                       const float* __restrict__ kv,
                       const float* __restrict__ ckv, int ldckv,
                       const float* __restrict__ cosT, const float* __restrict__ sinT,
                       const int* __restrict__ pos,
                       half* __restrict__ qfh, half* __restrict__ qfl,
                       half* __restrict__ kk, half* __restrict__ vt) {
    const int s = blockIdx.x;
    const int p = pos[s];
    const float* c  = cosT + (size_t)p * DROPE;
    const float* sn = sinT + (size_t)p * DROPE;

    for (int i = threadIdx.x; i < NH * DQK; i += 256) {
        int h = i / DQK, d = i % DQK;
        const float* qr = q + (size_t)s * NH * DQK + h * DQK;
        float val;
        if (d < DNOPE) val = qr[d];
        else {
            int dr = d - DNOPE;
            float x  = qr[d];
            float rh = (dr < DROPE / 2) ? -qr[DNOPE + dr + DROPE / 2]
                                        :  qr[DNOPE + dr - DROPE / 2];
            val = x * c[dr] + rh * sn[dr];
        }
        half hh, ll;
        hsplit(val, hh, ll);
        size_t o = ((size_t)h * SEQ + s) * DQK + d;
        qfh[o] = hh; qfl[o] = ll;
    }
    for (int i = threadIdx.x; i < NKV * DQK; i += 256) {
        int kh2 = i / DQK, d = i % DQK;
        float val;
        if (d < DNOPE) val = kv[(size_t)s * NKV * (DNOPE + DV) + kh2 * (DNOPE + DV) + d];
        else {
            int dr = d - DNOPE;
            const float* kr = ckv + (size_t)s * ldckv + KVRANK;
            float x  = kr[dr];
            float rh = (dr < DROPE / 2) ? -kr[dr + DROPE / 2] : kr[dr - DROPE / 2];
            val = x * c[dr] + rh * sn[dr];
        }
        kk[((size_t)kh2 * SEQ + s) * DQK + d] = __float2half_rn(val);
    }
    for (int i = threadIdx.x; i < NKV * DV; i += 256) {
        int kh2 = i / DV, d = i % DV;
        float val = kv[(size_t)s * NKV * (DNOPE + DV) + kh2 * (DNOPE + DV) + DNOPE + d];
        vt[((size_t)kh2 * DV + d) * SEQ + s] = __float2half_rn(val);
    }
}

// ---------------- launch ----------------
extern "C" void kernel_launch(void* const* d_in, const int* in_sizes, int n_in,
                              void* d_out, int out_size) {
    const float* hidden    = (const float*)d_in[0];
    const float* cosT      = (const float*)d_in[1];
    const float* sinT      = (const float*)d_in[2];
    const float* wq_a      = (const float*)d_in[3];
    const float* q_a_ln_w  = (const float*)d_in[4];
    const float* wq_b      = (const float*)d_in[5];
    const float* wkv_a     = (const float*)d_in[6];
    const float* kv_a_ln_w = (const float*)d_in[7];
    const float* wkv_b     = (const float*)d_in[8];
    const float* wo        = (const float*)d_in[9];
    const int*   cpos      = (const int*)d_in[10];
    float* out = (float*)d_out;

    float *qackv, *q, *kv;
    half *hidh, *hidl, *qanh, *qanl, *ckvnh, *ckvnl, *qfh, *qfl, *kk, *vt;
    half *ao;
    half *wcombT, *wqbT, *wkvbT, *woT;

    cudaGetSymbolAddress((void**)&qackv, g_qackv);
    cudaGetSymbolAddress((void**)&q,     g_q);
    cudaGetSymbolAddress((void**)&kv,    g_kv);
    cudaGetSymbolAddress((void**)&hidh,  g_hid_h);  cudaGetSymbolAddress((void**)&hidl,  g_hid_l);
    cudaGetSymbolAddress((void**)&qanh,  g_qan_h);  cudaGetSymbolAddress((void**)&qanl,  g_qan_l);
    cudaGetSymbolAddress((void**)&ckvnh, g_ckvn_h); cudaGetSymbolAddress((void**)&ckvnl, g_ckvn_l);
    cudaGetSymbolAddress((void**)&qfh,   g_qf_h);   cudaGetSymbolAddress((void**)&qfl,   g_qf_l);
    cudaGetSymbolAddress((void**)&kk,    g_k);
    cudaGetSymbolAddress((void**)&vt,    g_vT);
    cudaGetSymbolAddress((void**)&ao,    g_ao);
    cudaGetSymbolAddress((void**)&wcombT,g_wcombT);
    cudaGetSymbolAddress((void**)&wqbT,  g_wqbT);
    cudaGetSymbolAddress((void**)&wkvbT, g_wkvbT);
    cudaGetSymbolAddress((void**)&woT,   g_woT);

    cudaFuncSetAttribute(ntgemm<false,false>,
        cudaFuncAttributeMaxDynamicSharedMemorySize, DSMEM);
    cudaFuncSetAttribute(ntgemm<true,false>,
        cudaFuncAttributeMaxDynamicSharedMemorySize, DSMEM);
    cudaFuncSetAttribute(ntgemm<false,true>,
        cudaFuncAttributeMaxDynamicSharedMemorySize, DSMEM);
    cudaFuncSetAttribute(flash_attn,
        cudaFuncAttributeMaxDynamicSharedMemorySize, FA_SMEM);

    // 0) operand conversion
    split_pair<<<SEQ*DM/1024, 256>>>(hidden, hidh, hidl, SEQ*DM);
    wsplitT<<<dim3(QRANK/32, DM/32), 256>>>(wq_a,  wcombT, DM, QRANK, 0);
    wsplitT<<<dim3(18, DM/32), 256>>>(wkv_a, wcombT, DM, KVRANK+DROPE, QRANK);
    wsplitT<<<dim3(NH*DQK/32, QRANK/32), 256>>>(wq_b, wqbT, QRANK, NH*DQK, 0);
    wsplitT<<<dim3(NKV*(DNOPE+DV)/32, KVRANK/32), 256>>>(wkv_b, wkvbT, KVRANK, NKV*(DNOPE+DV), 0);
    wsplitT<<<dim3(DM/32, NH*DV/32), 256>>>(wo, woT, NH*DV, DM, 0);

    // 1) [q_a | ckv] = hidden @ [wq_a | wkv_a]   (fused, single 92%-fill wave)
    ntgemm<true,false><<<dim3(NCOMB/128, SEQ/128), 256, DSMEM>>>(
        hidh, hidl, wcombT, qackv, NVALID, DM, DM, DM, NCOMB);
    // 2) rmsnorms -> fp16 splits
    rmsnorm_split<<<SEQ, 256>>>(qackv, qanh, qanl, q_a_ln_w, QRANK, NCOMB, QRANK);
    rmsnorm_split<<<SEQ, 256>>>(qackv + QRANK, ckvnh, ckvnl, kv_a_ln_w,
                                KVRANK, NCOMB, KVRANK);
    // 3) q = qan @ wq_b
    ntgemm<false,false><<<dim3(NH*DQK/128, SEQ/128), 256, DSMEM>>>(
        qanh, qanl, wqbT, q, NH*DQK, QRANK, QRANK, QRANK, NH*DQK);
    // 4) kv = ckvn @ wkv_b
    ntgemm<false,false><<<dim3(NKV*(DNOPE+DV)/128, SEQ/128), 256, DSMEM>>>(
        ckvnh, ckvnl, wkvbT, kv, NKV*(DNOPE+DV), KVRANK, KVRANK, KVRANK, NKV*(DNOPE+DV));
    // 5) RoPE + gather -> fp16 (Q split; K,V single; V transposed)
    rope_gather_split<<<SEQ, 256>>>(q, kv, qackv + QRANK, NCOMB,
                                    cosT, sinT, cpos, qfh, qfl, kk, vt);
    // 6) fused flash attention -> ao single fp16 (1-pass PV)
    flash_attn<<<dim3(8, NH), 256, FA_SMEM>>>(
        qfh, qfl, kk, vt, ao, rsqrtf((float)DQK));
    // 7) out = ao @ wo  (1-pass A)
    ntgemm<false,true><<<dim3(DM/128, SEQ/128), 256, DSMEM>>>(
        ao, ao, woT, out, DM, NH*DV, NH*DV, NH*DV, DM);
}